// round 1
// baseline (speedup 1.0000x reference)
#include <cuda_runtime.h>
#include <math.h>

// Problem constants
#define TQ 2048
#define BB 2
#define EE 1024
#define HH 16
#define DD 64
#define TB 4096          // TQ*BB
#define FF 3072          // 3*EE

// Scratch (allocation-free rule: __device__ globals)
__device__ float g_q[(size_t)BB * HH * TQ * DD];   // 16 MB, pre-scaled by d^-0.5
__device__ float g_k[(size_t)BB * HH * TQ * DD];   // 16 MB
__device__ float g_v[(size_t)BB * HH * TQ * DD];   // 16 MB
__device__ float g_ctx[(size_t)TB * EE];           // 16 MB

// ============================================================================
// SGEMM: C[M,N] = A[M,K] * W[N,K]^T + bias   (K = 1024)
// 128x128 block tile, K-tile 16, 256 threads, 8x8 microtile.
// MODE 0: A = query, scatter C into g_q/g_k/g_v (q scaled by 0.125)
// MODE 1: A = g_ctx, C -> Cout (final output) row-major [TB, EE]
// ============================================================================
template <int MODE>
__global__ __launch_bounds__(256, 2)
void sgemm_kernel(const float* __restrict__ A,
                  const float* __restrict__ W,
                  const float* __restrict__ bias,
                  float* __restrict__ Cout)
{
    const int K = EE;
    __shared__ float sA[16 * 132];
    __shared__ float sB[16 * 132];

    const float* __restrict__ Ap = (MODE == 0) ? A : g_ctx;

    const int row0 = blockIdx.y * 128;
    const int col0 = blockIdx.x * 128;
    const int tid  = threadIdx.x;
    const int ty   = tid >> 4;
    const int tx   = tid & 15;

    float acc[8][8];
#pragma unroll
    for (int i = 0; i < 8; i++)
#pragma unroll
        for (int j = 0; j < 8; j++) acc[i][j] = 0.0f;

    for (int kt = 0; kt < K; kt += 16) {
#pragma unroll
        for (int p = 0; p < 2; p++) {
            int id = tid + p * 256;
            int r  = id >> 2;
            int c4 = (id & 3) << 2;
            float4 av = *(const float4*)(Ap + (size_t)(row0 + r) * K + kt + c4);
            sA[(c4 + 0) * 132 + r] = av.x;
            sA[(c4 + 1) * 132 + r] = av.y;
            sA[(c4 + 2) * 132 + r] = av.z;
            sA[(c4 + 3) * 132 + r] = av.w;
            float4 wv = *(const float4*)(W + (size_t)(col0 + r) * K + kt + c4);
            sB[(c4 + 0) * 132 + r] = wv.x;
            sB[(c4 + 1) * 132 + r] = wv.y;
            sB[(c4 + 2) * 132 + r] = wv.z;
            sB[(c4 + 3) * 132 + r] = wv.w;
        }
        __syncthreads();

#pragma unroll
        for (int k = 0; k < 16; k++) {
            float a[8], b[8];
            *(float4*)&a[0] = *(const float4*)&sA[k * 132 + 8 * ty];
            *(float4*)&a[4] = *(const float4*)&sA[k * 132 + 8 * ty + 4];
            *(float4*)&b[0] = *(const float4*)&sB[k * 132 + 8 * tx];
            *(float4*)&b[4] = *(const float4*)&sB[k * 132 + 8 * tx + 4];
#pragma unroll
            for (int i = 0; i < 8; i++)
#pragma unroll
                for (int j = 0; j < 8; j++)
                    acc[i][j] = fmaf(a[i], b[j], acc[i][j]);
        }
        __syncthreads();
    }

    if (MODE == 0) {
        // f = h*192 + which*64 + dd  ;  dst layout [B][H][T][64]
#pragma unroll
        for (int j = 0; j < 8; j++) {
            int f     = col0 + 8 * tx + j;
            float bv  = bias[f];
            int h     = f / 192;
            int rem   = f - h * 192;
            int which = rem >> 6;
            int dd    = rem & 63;
            float* dst = (which == 0) ? g_q : ((which == 1) ? g_k : g_v);
            float mul  = (which == 0) ? 0.125f : 1.0f;  // scaling = 64^-0.5
#pragma unroll
            for (int i = 0; i < 8; i++) {
                int tb = row0 + 8 * ty + i;
                int t  = tb >> 1;
                int b  = tb & 1;
                dst[((size_t)(b * HH + h) * TQ + t) * DD + dd] = (acc[i][j] + bv) * mul;
            }
        }
    } else {
#pragma unroll
        for (int i = 0; i < 8; i++) {
            int tb = row0 + 8 * ty + i;
#pragma unroll
            for (int j = 0; j < 8; j++) {
                int f = col0 + 8 * tx + j;
                Cout[(size_t)tb * EE + f] = acc[i][j] + bias[f];
            }
        }
    }
}

// ============================================================================
// Flash attention (fp32, d=64). One CTA: 64 query rows of one (b,h).
// 256 threads = 16x16, 4x4 microtile over the 64x64 S / O tiles.
// Online softmax; row groups = 16 consecutive lanes -> shfl_xor reductions.
// Writes ctx into [TB, EE] layout for the out-proj GEMM.
// ============================================================================
#define ATTN_SMEM_FLOATS (3 * 64 * 68 + 64 * 65)

__global__ __launch_bounds__(256)
void attn_kernel()
{
    extern __shared__ float sm[];
    float* Qt = sm;                  // [e][r], stride 68
    float* Ks = sm + 64 * 68;        // [e][s], stride 68
    float* Vs = sm + 2 * 64 * 68;    // [s][d], stride 68
    float* Pt = sm + 3 * 64 * 68;    // [s][r], stride 65

    const int bh   = blockIdx.y;         // b*HH + h
    const size_t base = (size_t)bh * TQ * DD;
    const int b    = bh >> 4;
    const int h    = bh & 15;
    const int t0   = blockIdx.x * 64;
    const int tid  = threadIdx.x;
    const int ty   = tid >> 4;
    const int tx   = tid & 15;

    // Load Q tile transposed (already scaled in projection)
#pragma unroll
    for (int p = 0; p < 4; p++) {
        int id = tid + p * 256;
        int r  = id >> 4;
        int e4 = (id & 15) << 2;
        float4 qv = *(const float4*)(g_q + base + (size_t)(t0 + r) * DD + e4);
        Qt[(e4 + 0) * 68 + r] = qv.x;
        Qt[(e4 + 1) * 68 + r] = qv.y;
        Qt[(e4 + 2) * 68 + r] = qv.z;
        Qt[(e4 + 3) * 68 + r] = qv.w;
    }

    float m[4], l[4], O[4][4];
#pragma unroll
    for (int i = 0; i < 4; i++) {
        m[i] = -1e30f;
        l[i] = 0.0f;
#pragma unroll
        for (int j = 0; j < 4; j++) O[i][j] = 0.0f;
    }

    for (int st = 0; st < TQ; st += 64) {
        // Load K (transposed) and V tiles
#pragma unroll
        for (int p = 0; p < 4; p++) {
            int id = tid + p * 256;
            int s  = id >> 4;
            int e4 = (id & 15) << 2;
            float4 kv = *(const float4*)(g_k + base + (size_t)(st + s) * DD + e4);
            Ks[(e4 + 0) * 68 + s] = kv.x;
            Ks[(e4 + 1) * 68 + s] = kv.y;
            Ks[(e4 + 2) * 68 + s] = kv.z;
            Ks[(e4 + 3) * 68 + s] = kv.w;
            float4 vv = *(const float4*)(g_v + base + (size_t)(st + s) * DD + e4);
            *(float4*)(Vs + s * 68 + e4) = vv;
        }
        __syncthreads();

        // S = Q K^T  (4x4 per thread)
        float S[4][4];
#pragma unroll
        for (int i = 0; i < 4; i++)
#pragma unroll
            for (int j = 0; j < 4; j++) S[i][j] = 0.0f;

#pragma unroll 16
        for (int e = 0; e < 64; e++) {
            float4 aq = *(const float4*)(Qt + e * 68 + 4 * ty);
            float4 bk = *(const float4*)(Ks + e * 68 + 4 * tx);
            float a[4] = {aq.x, aq.y, aq.z, aq.w};
            float c[4] = {bk.x, bk.y, bk.z, bk.w};
#pragma unroll
            for (int i = 0; i < 4; i++)
#pragma unroll
                for (int j = 0; j < 4; j++)
                    S[i][j] = fmaf(a[i], c[j], S[i][j]);
        }

        // Online softmax per row (16-lane groups share ty within a warp)
#pragma unroll
        for (int i = 0; i < 4; i++) {
            float mx = fmaxf(fmaxf(S[i][0], S[i][1]), fmaxf(S[i][2], S[i][3]));
            mx = fmaxf(mx, __shfl_xor_sync(0xffffffffu, mx, 1));
            mx = fmaxf(mx, __shfl_xor_sync(0xffffffffu, mx, 2));
            mx = fmaxf(mx, __shfl_xor_sync(0xffffffffu, mx, 4));
            mx = fmaxf(mx, __shfl_xor_sync(0xffffffffu, mx, 8));
            float mnew = fmaxf(m[i], mx);
            float sc   = __expf(m[i] - mnew);
            float sum  = 0.0f;
#pragma unroll
            for (int j = 0; j < 4; j++) {
                S[i][j] = __expf(S[i][j] - mnew);
                sum += S[i][j];
            }
            sum += __shfl_xor_sync(0xffffffffu, sum, 1);
            sum += __shfl_xor_sync(0xffffffffu, sum, 2);
            sum += __shfl_xor_sync(0xffffffffu, sum, 4);
            sum += __shfl_xor_sync(0xffffffffu, sum, 8);
            l[i] = l[i] * sc + sum;
            m[i] = mnew;
#pragma unroll
            for (int j = 0; j < 4; j++) O[i][j] *= sc;
        }

        // Stage P transposed for the O GEMM
#pragma unroll
        for (int j = 0; j < 4; j++)
#pragma unroll
            for (int i = 0; i < 4; i++)
                Pt[(4 * tx + j) * 65 + 4 * ty + i] = S[i][j];
        __syncthreads();

        // O += P V
#pragma unroll 16
        for (int s = 0; s < 64; s++) {
            float a0 = Pt[s * 65 + 4 * ty + 0];
            float a1 = Pt[s * 65 + 4 * ty + 1];
            float a2 = Pt[s * 65 + 4 * ty + 2];
            float a3 = Pt[s * 65 + 4 * ty + 3];
            float4 bv = *(const float4*)(Vs + s * 68 + 4 * tx);
            O[0][0] = fmaf(a0, bv.x, O[0][0]); O[0][1] = fmaf(a0, bv.y, O[0][1]);
            O[0][2] = fmaf(a0, bv.z, O[0][2]); O[0][3] = fmaf(a0, bv.w, O[0][3]);
            O[1][0] = fmaf(a1, bv.x, O[1][0]); O[1][1] = fmaf(a1, bv.y, O[1][1]);
            O[1][2] = fmaf(a1, bv.z, O[1][2]); O[1][3] = fmaf(a1, bv.w, O[1][3]);
            O[2][0] = fmaf(a2, bv.x, O[2][0]); O[2][1] = fmaf(a2, bv.y, O[2][1]);
            O[2][2] = fmaf(a2, bv.z, O[2][2]); O[2][3] = fmaf(a2, bv.w, O[2][3]);
            O[3][0] = fmaf(a3, bv.x, O[3][0]); O[3][1] = fmaf(a3, bv.y, O[3][1]);
            O[3][2] = fmaf(a3, bv.z, O[3][2]); O[3][3] = fmaf(a3, bv.w, O[3][3]);
        }
        __syncthreads();   // before next tile overwrites Ks/Vs
    }

    // Normalize and write ctx in [TB, EE] layout
#pragma unroll
    for (int i = 0; i < 4; i++) {
        float inv = 1.0f / l[i];
        int t = t0 + 4 * ty + i;
        size_t row = (size_t)(t * BB + b) * EE + h * 64 + 4 * tx;
        float4 o = make_float4(O[i][0] * inv, O[i][1] * inv, O[i][2] * inv, O[i][3] * inv);
        *(float4*)(g_ctx + row) = o;
    }
}

// ============================================================================
// Launch
// ============================================================================
extern "C" void kernel_launch(void* const* d_in, const int* in_sizes, int n_in,
                              void* d_out, int out_size)
{
    const float* query = (const float*)d_in[0];
    const float* w_in  = (const float*)d_in[1];
    const float* b_in  = (const float*)d_in[2];
    const float* w_out = (const float*)d_in[3];
    const float* b_out = (const float*)d_in[4];
    float* out = (float*)d_out;

    const int attn_smem = ATTN_SMEM_FLOATS * (int)sizeof(float);  // 68864 B
    cudaFuncSetAttribute(attn_kernel, cudaFuncAttributeMaxDynamicSharedMemorySize, attn_smem);

    // 1) QKV projection + bias + scale + scatter to [B,H,T,64]
    sgemm_kernel<0><<<dim3(FF / 128, TB / 128), 256>>>(query, w_in, b_in, nullptr);
    // 2) Flash attention -> ctx [TB, EE]
    attn_kernel<<<dim3(TQ / 64, BB * HH), 256, attn_smem>>>();
    // 3) Output projection + bias -> d_out
    sgemm_kernel<1><<<dim3(EE / 128, TB / 128), 256>>>(nullptr, w_out, b_out, out);
}

// round 3
// speedup vs baseline: 1.2825x; 1.2825x over previous
#include <cuda_runtime.h>
#include <cuda_bf16.h>
#include <math.h>
#include <cstdint>

// Problem constants
#define TQ 2048
#define BB 2
#define EE 1024
#define HH 16
#define DD 64
#define TB 4096          // TQ*BB
#define FF 3072          // 3*EE

// Scratch (allocation-free rule: __device__ globals)
__device__ float g_q[(size_t)BB * HH * TQ * DD];   // 16 MB, pre-scaled by d^-0.5
__device__ float g_k[(size_t)BB * HH * TQ * DD];   // 16 MB
__device__ float g_v[(size_t)BB * HH * TQ * DD];   // 16 MB
__device__ float g_ctx[(size_t)TB * EE];           // 16 MB

// ============================================================================
// bf16 helpers
// ============================================================================
__device__ __forceinline__ uint32_t pack2(__nv_bfloat16 a, __nv_bfloat16 b) {
    uint16_t ua = *(uint16_t*)&a, ub = *(uint16_t*)&b;
    return (uint32_t)ua | ((uint32_t)ub << 16);
}
// split (x,y) into packed bf16 hi and lo words (x in low half)
__device__ __forceinline__ void split2(float x, float y, uint32_t& hi, uint32_t& lo) {
    __nv_bfloat16 hx = __float2bfloat16(x), hy = __float2bfloat16(y);
    __nv_bfloat16 lx = __float2bfloat16(x - __bfloat162float(hx));
    __nv_bfloat16 ly = __float2bfloat16(y - __bfloat162float(hy));
    hi = pack2(hx, hy);
    lo = pack2(lx, ly);
}

// mma.sync m16n8k16 row.col f32 += bf16*bf16
__device__ __forceinline__ void mma_bf16(float* d, const uint32_t* a, const uint32_t* b) {
    asm volatile(
        "mma.sync.aligned.m16n8k16.row.col.f32.bf16.bf16.f32 "
        "{%0,%1,%2,%3}, {%4,%5,%6,%7}, {%8,%9}, {%0,%1,%2,%3};"
        : "+f"(d[0]), "+f"(d[1]), "+f"(d[2]), "+f"(d[3])
        : "r"(a[0]), "r"(a[1]), "r"(a[2]), "r"(a[3]), "r"(b[0]), "r"(b[1]));
}

// ============================================================================
// Tensor-core SGEMM (legacy mma.sync, bf16x3): C[M,N] = A[M,K]*W[N,K]^T + bias
// 128x128 CTA tile, 8 warps (2m x 4n), warp tile 64x32, atoms m16n8k16.
// K-chunk 32, double-buffered smem, LDG prefetch overlapped with mma.
// MODE 0: A = query, scatter into g_q/g_k/g_v (q scaled by 0.125)
// MODE 1: A = g_ctx, C -> Cout [TB, EE]
// ============================================================================
#define BK 32
#define NC (EE / BK)          // 32 chunks
#define ROWB 72               // bytes per smem row (32 bf16 = 64B + 8B pad)
#define MAT_BYTES (128 * ROWB)      // 9216
#define STAGE_BYTES (4 * MAT_BYTES) // Ahi, Alo, Bhi, Blo = 36864
#define GEMM_SMEM (2 * STAGE_BYTES) // 73728

template <int MODE>
__global__ __launch_bounds__(256, 1)
void mma_gemm_kernel(const float* __restrict__ A,
                     const float* __restrict__ W,
                     const float* __restrict__ bias,
                     float* __restrict__ Cout)
{
    extern __shared__ char smem[];

    const int tid  = threadIdx.x;
    const int wid  = tid >> 5;
    const int lane = tid & 31;
    const int g    = lane >> 2;    // group id 0..7
    const int t    = lane & 3;     // thread-in-group 0..3

    const int wm = (wid >> 2) << 6;   // warp row offset: 0 or 64
    const int wn = (wid & 3) << 5;    // warp col offset: 0/32/64/96

    const float* __restrict__ Asrc = (MODE == 0) ? A : g_ctx;
    const int row0 = blockIdx.y * 128;
    const int col0 = blockIdx.x * 128;

    float acc[4][4][4];
#pragma unroll
    for (int i = 0; i < 4; i++)
#pragma unroll
        for (int j = 0; j < 4; j++)
#pragma unroll
            for (int k = 0; k < 4; k++) acc[i][j][k] = 0.0f;

    float4 pa[4], pw[4];

    // ---- global prefetch of one K-chunk into registers ----
    auto ldg_chunk = [&](int kt) {
#pragma unroll
        for (int p = 0; p < 4; p++) {
            int id = tid + p * 256;
            int r  = id >> 3;
            int cg = (id & 7) << 2;
            pa[p] = *(const float4*)(Asrc + (size_t)(row0 + r) * EE + kt + cg);
            pw[p] = *(const float4*)(W + (size_t)(col0 + r) * EE + kt + cg);
        }
    };

    // ---- convert + store prefetched chunk to a smem stage ----
    auto sts_chunk = [&](int stage) {
        char* base = smem + stage * STAGE_BYTES;
#pragma unroll
        for (int p = 0; p < 4; p++) {
            int id = tid + p * 256;
            int r  = id >> 3;
            int cg = id & 7;
            int off = r * ROWB + cg * 8;
            uint32_t h0, l0, h1, l1;
            split2(pa[p].x, pa[p].y, h0, l0);
            split2(pa[p].z, pa[p].w, h1, l1);
            *(uint2*)(base + 0 * MAT_BYTES + off) = make_uint2(h0, h1);
            *(uint2*)(base + 1 * MAT_BYTES + off) = make_uint2(l0, l1);
            split2(pw[p].x, pw[p].y, h0, l0);
            split2(pw[p].z, pw[p].w, h1, l1);
            *(uint2*)(base + 2 * MAT_BYTES + off) = make_uint2(h0, h1);
            *(uint2*)(base + 3 * MAT_BYTES + off) = make_uint2(l0, l1);
        }
    };

    // ---- compute one K-chunk from a smem stage (3 bf16 passes) ----
    auto compute = [&](int stage) {
        const char* Ah = smem + stage * STAGE_BYTES + 0 * MAT_BYTES;
        const char* Al = smem + stage * STAGE_BYTES + 1 * MAT_BYTES;
        const char* Bh = smem + stage * STAGE_BYTES + 2 * MAT_BYTES;
        const char* Bl = smem + stage * STAGE_BYTES + 3 * MAT_BYTES;
#pragma unroll
        for (int ks = 0; ks < 2; ks++) {
            const int kb = ks * 32 + t * 4;   // byte offset of k=(k0+2t) within row
            uint32_t afh[4][4], afl[4][4];
#pragma unroll
            for (int ma = 0; ma < 4; ma++) {
                int ro = (wm + 16 * ma + g) * ROWB + kb;
                afh[ma][0] = *(const uint32_t*)(Ah + ro);
                afh[ma][1] = *(const uint32_t*)(Ah + ro + 8 * ROWB);
                afh[ma][2] = *(const uint32_t*)(Ah + ro + 16);
                afh[ma][3] = *(const uint32_t*)(Ah + ro + 8 * ROWB + 16);
                afl[ma][0] = *(const uint32_t*)(Al + ro);
                afl[ma][1] = *(const uint32_t*)(Al + ro + 8 * ROWB);
                afl[ma][2] = *(const uint32_t*)(Al + ro + 16);
                afl[ma][3] = *(const uint32_t*)(Al + ro + 8 * ROWB + 16);
            }
            uint32_t bfh[4][2], bfl[4][2];
#pragma unroll
            for (int na = 0; na < 4; na++) {
                int ro = (wn + 8 * na + g) * ROWB + kb;
                bfh[na][0] = *(const uint32_t*)(Bh + ro);
                bfh[na][1] = *(const uint32_t*)(Bh + ro + 16);
                bfl[na][0] = *(const uint32_t*)(Bl + ro);
                bfl[na][1] = *(const uint32_t*)(Bl + ro + 16);
            }
#pragma unroll
            for (int ma = 0; ma < 4; ma++)
#pragma unroll
                for (int na = 0; na < 4; na++)
                    mma_bf16(acc[ma][na], afh[ma], bfh[na]);
#pragma unroll
            for (int ma = 0; ma < 4; ma++)
#pragma unroll
                for (int na = 0; na < 4; na++)
                    mma_bf16(acc[ma][na], afh[ma], bfl[na]);
#pragma unroll
            for (int ma = 0; ma < 4; ma++)
#pragma unroll
                for (int na = 0; na < 4; na++)
                    mma_bf16(acc[ma][na], afl[ma], bfh[na]);
        }
    };

    // ---- pipelined main loop ----
    ldg_chunk(0);
    sts_chunk(0);
    for (int c = 0; c < NC; c++) {
        __syncthreads();                    // stage c&1 ready for all warps
        if (c + 1 < NC) ldg_chunk((c + 1) * BK);
        compute(c & 1);
        if (c + 1 < NC) sts_chunk((c + 1) & 1);
    }

    // ---- epilogue: regs -> gmem (float2 stores, 32B segments = full sectors)
#pragma unroll
    for (int na = 0; na < 4; na++) {
        const int f0 = col0 + wn + 8 * na + 2 * t;
        const float b0 = bias[f0];
        const float b1 = bias[f0 + 1];
        if (MODE == 0) {
            int h     = f0 / 192;
            int rem   = f0 - 192 * h;
            int which = rem >> 6;
            int dd    = rem & 63;
            float* dst = (which == 0) ? g_q : ((which == 1) ? g_k : g_v);
            float mul  = (which == 0) ? 0.125f : 1.0f;
#pragma unroll
            for (int ma = 0; ma < 4; ma++) {
                const float* d4 = acc[ma][na];
                int tb = row0 + wm + 16 * ma + g;
                {
                    int tt = tb >> 1, bb = tb & 1;
                    *(float2*)(dst + ((size_t)(bb * HH + h) * TQ + tt) * DD + dd) =
                        make_float2((d4[0] + b0) * mul, (d4[1] + b1) * mul);
                }
                {
                    int tb2 = tb + 8;
                    int tt = tb2 >> 1, bb = tb2 & 1;
                    *(float2*)(dst + ((size_t)(bb * HH + h) * TQ + tt) * DD + dd) =
                        make_float2((d4[2] + b0) * mul, (d4[3] + b1) * mul);
                }
            }
        } else {
#pragma unroll
            for (int ma = 0; ma < 4; ma++) {
                const float* d4 = acc[ma][na];
                int r = row0 + wm + 16 * ma + g;
                *(float2*)(Cout + (size_t)r * EE + f0) =
                    make_float2(d4[0] + b0, d4[1] + b1);
                *(float2*)(Cout + (size_t)(r + 8) * EE + f0) =
                    make_float2(d4[2] + b0, d4[3] + b1);
            }
        }
    }
}

// ============================================================================
// Flash attention (fp32, d=64) — unchanged (round-1 validated)
// ============================================================================
#define ATTN_SMEM_FLOATS (3 * 64 * 68 + 64 * 65)

__global__ __launch_bounds__(256)
void attn_kernel()
{
    extern __shared__ float sm[];
    float* Qt = sm;                  // [e][r], stride 68
    float* Ks = sm + 64 * 68;        // [e][s], stride 68
    float* Vs = sm + 2 * 64 * 68;    // [s][d], stride 68
    float* Pt = sm + 3 * 64 * 68;    // [s][r], stride 65

    const int bh   = blockIdx.y;
    const size_t base = (size_t)bh * TQ * DD;
    const int b    = bh >> 4;
    const int h    = bh & 15;
    const int t0   = blockIdx.x * 64;
    const int tid  = threadIdx.x;
    const int ty   = tid >> 4;
    const int tx   = tid & 15;

#pragma unroll
    for (int p = 0; p < 4; p++) {
        int id = tid + p * 256;
        int r  = id >> 4;
        int e4 = (id & 15) << 2;
        float4 qv = *(const float4*)(g_q + base + (size_t)(t0 + r) * DD + e4);
        Qt[(e4 + 0) * 68 + r] = qv.x;
        Qt[(e4 + 1) * 68 + r] = qv.y;
        Qt[(e4 + 2) * 68 + r] = qv.z;
        Qt[(e4 + 3) * 68 + r] = qv.w;
    }

    float m[4], l[4], O[4][4];
#pragma unroll
    for (int i = 0; i < 4; i++) {
        m[i] = -1e30f;
        l[i] = 0.0f;
#pragma unroll
        for (int j = 0; j < 4; j++) O[i][j] = 0.0f;
    }

    for (int st = 0; st < TQ; st += 64) {
#pragma unroll
        for (int p = 0; p < 4; p++) {
            int id = tid + p * 256;
            int s  = id >> 4;
            int e4 = (id & 15) << 2;
            float4 kv = *(const float4*)(g_k + base + (size_t)(st + s) * DD + e4);
            Ks[(e4 + 0) * 68 + s] = kv.x;
            Ks[(e4 + 1) * 68 + s] = kv.y;
            Ks[(e4 + 2) * 68 + s] = kv.z;
            Ks[(e4 + 3) * 68 + s] = kv.w;
            float4 vv = *(const float4*)(g_v + base + (size_t)(st + s) * DD + e4);
            *(float4*)(Vs + s * 68 + e4) = vv;
        }
        __syncthreads();

        float S[4][4];
#pragma unroll
        for (int i = 0; i < 4; i++)
#pragma unroll
            for (int j = 0; j < 4; j++) S[i][j] = 0.0f;

#pragma unroll 16
        for (int e = 0; e < 64; e++) {
            float4 aq = *(const float4*)(Qt + e * 68 + 4 * ty);
            float4 bk = *(const float4*)(Ks + e * 68 + 4 * tx);
            float a[4] = {aq.x, aq.y, aq.z, aq.w};
            float c[4] = {bk.x, bk.y, bk.z, bk.w};
#pragma unroll
            for (int i = 0; i < 4; i++)
#pragma unroll
                for (int j = 0; j < 4; j++)
                    S[i][j] = fmaf(a[i], c[j], S[i][j]);
        }

#pragma unroll
        for (int i = 0; i < 4; i++) {
            float mx = fmaxf(fmaxf(S[i][0], S[i][1]), fmaxf(S[i][2], S[i][3]));
            mx = fmaxf(mx, __shfl_xor_sync(0xffffffffu, mx, 1));
            mx = fmaxf(mx, __shfl_xor_sync(0xffffffffu, mx, 2));
            mx = fmaxf(mx, __shfl_xor_sync(0xffffffffu, mx, 4));
            mx = fmaxf(mx, __shfl_xor_sync(0xffffffffu, mx, 8));
            float mnew = fmaxf(m[i], mx);
            float sc   = __expf(m[i] - mnew);
            float sum  = 0.0f;
#pragma unroll
            for (int j = 0; j < 4; j++) {
                S[i][j] = __expf(S[i][j] - mnew);
                sum += S[i][j];
            }
            sum += __shfl_xor_sync(0xffffffffu, sum, 1);
            sum += __shfl_xor_sync(0xffffffffu, sum, 2);
            sum += __shfl_xor_sync(0xffffffffu, sum, 4);
            sum += __shfl_xor_sync(0xffffffffu, sum, 8);
            l[i] = l[i] * sc + sum;
            m[i] = mnew;
#pragma unroll
            for (int j = 0; j < 4; j++) O[i][j] *= sc;
        }

#pragma unroll
        for (int j = 0; j < 4; j++)
#pragma unroll
            for (int i = 0; i < 4; i++)
                Pt[(4 * tx + j) * 65 + 4 * ty + i] = S[i][j];
        __syncthreads();

#pragma unroll 16
        for (int s = 0; s < 64; s++) {
            float a0 = Pt[s * 65 + 4 * ty + 0];
            float a1 = Pt[s * 65 + 4 * ty + 1];
            float a2 = Pt[s * 65 + 4 * ty + 2];
            float a3 = Pt[s * 65 + 4 * ty + 3];
            float4 bv = *(const float4*)(Vs + s * 68 + 4 * tx);
            O[0][0] = fmaf(a0, bv.x, O[0][0]); O[0][1] = fmaf(a0, bv.y, O[0][1]);
            O[0][2] = fmaf(a0, bv.z, O[0][2]); O[0][3] = fmaf(a0, bv.w, O[0][3]);
            O[1][0] = fmaf(a1, bv.x, O[1][0]); O[1][1] = fmaf(a1, bv.y, O[1][1]);
            O[1][2] = fmaf(a1, bv.z, O[1][2]); O[1][3] = fmaf(a1, bv.w, O[1][3]);
            O[2][0] = fmaf(a2, bv.x, O[2][0]); O[2][1] = fmaf(a2, bv.y, O[2][1]);
            O[2][2] = fmaf(a2, bv.z, O[2][2]); O[2][3] = fmaf(a2, bv.w, O[2][3]);
            O[3][0] = fmaf(a3, bv.x, O[3][0]); O[3][1] = fmaf(a3, bv.y, O[3][1]);
            O[3][2] = fmaf(a3, bv.z, O[3][2]); O[3][3] = fmaf(a3, bv.w, O[3][3]);
        }
        __syncthreads();
    }

#pragma unroll
    for (int i = 0; i < 4; i++) {
        float inv = 1.0f / l[i];
        int t = t0 + 4 * ty + i;
        size_t row = (size_t)(t * BB + b) * EE + h * 64 + 4 * tx;
        float4 o = make_float4(O[i][0] * inv, O[i][1] * inv, O[i][2] * inv, O[i][3] * inv);
        *(float4*)(g_ctx + row) = o;
    }
}

// ============================================================================
// Launch
// ============================================================================
extern "C" void kernel_launch(void* const* d_in, const int* in_sizes, int n_in,
                              void* d_out, int out_size)
{
    const float* query = (const float*)d_in[0];
    const float* w_in  = (const float*)d_in[1];
    const float* b_in  = (const float*)d_in[2];
    const float* w_out = (const float*)d_in[3];
    const float* b_out = (const float*)d_in[4];
    float* out = (float*)d_out;

    const int attn_smem = ATTN_SMEM_FLOATS * (int)sizeof(float);  // 68864 B
    cudaFuncSetAttribute(attn_kernel, cudaFuncAttributeMaxDynamicSharedMemorySize, attn_smem);
    cudaFuncSetAttribute(mma_gemm_kernel<0>, cudaFuncAttributeMaxDynamicSharedMemorySize, GEMM_SMEM);
    cudaFuncSetAttribute(mma_gemm_kernel<1>, cudaFuncAttributeMaxDynamicSharedMemorySize, GEMM_SMEM);

    // 1) QKV projection (mma.sync bf16x3) + bias + scale + scatter
    mma_gemm_kernel<0><<<dim3(FF / 128, TB / 128), 256, GEMM_SMEM>>>(query, w_in, b_in, nullptr);
    // 2) Flash attention -> ctx [TB, EE]
    attn_kernel<<<dim3(TQ / 64, BB * HH), 256, attn_smem>>>();
    // 3) Output projection (mma.sync bf16x3) + bias -> d_out
    mma_gemm_kernel<1><<<dim3(EE / 128, TB / 128), 256, GEMM_SMEM>>>(nullptr, w_out, b_out, out);
}

// round 4
// speedup vs baseline: 2.1398x; 1.6685x over previous
#include <cuda_runtime.h>
#include <cuda_bf16.h>
#include <math.h>
#include <cstdint>

// Problem constants
#define TQ 2048
#define BB 2
#define EE 1024
#define HH 16
#define DD 64
#define TB 4096          // TQ*BB
#define FF 3072          // 3*EE

// Scratch (allocation-free rule: __device__ globals)
__device__ float g_q[(size_t)BB * HH * TQ * DD];   // 16 MB, pre-scaled by d^-0.5
__device__ float g_k[(size_t)BB * HH * TQ * DD];   // 16 MB
__device__ float g_v[(size_t)BB * HH * TQ * DD];   // 16 MB
__device__ float g_ctx[(size_t)TB * EE];           // 16 MB

// ============================================================================
// helpers
// ============================================================================
__device__ __forceinline__ uint32_t smem_u32(const void* p) {
    uint32_t a;
    asm("{ .reg .u64 t; cvta.to.shared.u64 t, %1; cvt.u32.u64 %0, t; }" : "=r"(a) : "l"(p));
    return a;
}
__device__ __forceinline__ uint32_t pack2(__nv_bfloat16 a, __nv_bfloat16 b) {
    uint16_t ua = *(uint16_t*)&a, ub = *(uint16_t*)&b;
    return (uint32_t)ua | ((uint32_t)ub << 16);
}
// split (x,y) into packed bf16 hi and lo words (x in low half)
__device__ __forceinline__ void split2(float x, float y, uint32_t& hi, uint32_t& lo) {
    __nv_bfloat16 hx = __float2bfloat16(x), hy = __float2bfloat16(y);
    __nv_bfloat16 lx = __float2bfloat16(x - __bfloat162float(hx));
    __nv_bfloat16 ly = __float2bfloat16(y - __bfloat162float(hy));
    hi = pack2(hx, hy);
    lo = pack2(lx, ly);
}

// mma.sync m16n8k16 row.col f32 += bf16*bf16
__device__ __forceinline__ void mma_bf16(float* d, const uint32_t* a, const uint32_t* b) {
    asm volatile(
        "mma.sync.aligned.m16n8k16.row.col.f32.bf16.bf16.f32 "
        "{%0,%1,%2,%3}, {%4,%5,%6,%7}, {%8,%9}, {%0,%1,%2,%3};"
        : "+f"(d[0]), "+f"(d[1]), "+f"(d[2]), "+f"(d[3])
        : "r"(a[0]), "r"(a[1]), "r"(a[2]), "r"(a[3]), "r"(b[0]), "r"(b[1]));
}

#define LDSM_X4(R0,R1,R2,R3,ADDR) \
    asm volatile("ldmatrix.sync.aligned.m8n8.x4.shared.b16 {%0,%1,%2,%3}, [%4];" \
        : "=r"(R0), "=r"(R1), "=r"(R2), "=r"(R3) : "r"(ADDR))
#define LDSM_X4_T(R0,R1,R2,R3,ADDR) \
    asm volatile("ldmatrix.sync.aligned.m8n8.x4.trans.shared.b16 {%0,%1,%2,%3}, [%4];" \
        : "=r"(R0), "=r"(R1), "=r"(R2), "=r"(R3) : "r"(ADDR))

// ============================================================================
// Tensor-core SGEMM (legacy mma.sync, bf16x3) — unchanged from round 3
// ============================================================================
#define BK 32
#define NC (EE / BK)
#define ROWB 72
#define MAT_BYTES (128 * ROWB)
#define STAGE_BYTES (4 * MAT_BYTES)
#define GEMM_SMEM (2 * STAGE_BYTES)

template <int MODE>
__global__ __launch_bounds__(256, 1)
void mma_gemm_kernel(const float* __restrict__ A,
                     const float* __restrict__ W,
                     const float* __restrict__ bias,
                     float* __restrict__ Cout)
{
    extern __shared__ char smem[];

    const int tid  = threadIdx.x;
    const int wid  = tid >> 5;
    const int lane = tid & 31;
    const int g    = lane >> 2;
    const int t    = lane & 3;

    const int wm = (wid >> 2) << 6;
    const int wn = (wid & 3) << 5;

    const float* __restrict__ Asrc = (MODE == 0) ? A : g_ctx;
    const int row0 = blockIdx.y * 128;
    const int col0 = blockIdx.x * 128;

    float acc[4][4][4];
#pragma unroll
    for (int i = 0; i < 4; i++)
#pragma unroll
        for (int j = 0; j < 4; j++)
#pragma unroll
            for (int k = 0; k < 4; k++) acc[i][j][k] = 0.0f;

    float4 pa[4], pw[4];

    auto ldg_chunk = [&](int kt) {
#pragma unroll
        for (int p = 0; p < 4; p++) {
            int id = tid + p * 256;
            int r  = id >> 3;
            int cg = (id & 7) << 2;
            pa[p] = *(const float4*)(Asrc + (size_t)(row0 + r) * EE + kt + cg);
            pw[p] = *(const float4*)(W + (size_t)(col0 + r) * EE + kt + cg);
        }
    };

    auto sts_chunk = [&](int stage) {
        char* base = smem + stage * STAGE_BYTES;
#pragma unroll
        for (int p = 0; p < 4; p++) {
            int id = tid + p * 256;
            int r  = id >> 3;
            int cg = id & 7;
            int off = r * ROWB + cg * 8;
            uint32_t h0, l0, h1, l1;
            split2(pa[p].x, pa[p].y, h0, l0);
            split2(pa[p].z, pa[p].w, h1, l1);
            *(uint2*)(base + 0 * MAT_BYTES + off) = make_uint2(h0, h1);
            *(uint2*)(base + 1 * MAT_BYTES + off) = make_uint2(l0, l1);
            split2(pw[p].x, pw[p].y, h0, l0);
            split2(pw[p].z, pw[p].w, h1, l1);
            *(uint2*)(base + 2 * MAT_BYTES + off) = make_uint2(h0, h1);
            *(uint2*)(base + 3 * MAT_BYTES + off) = make_uint2(l0, l1);
        }
    };

    auto compute = [&](int stage) {
        const char* Ah = smem + stage * STAGE_BYTES + 0 * MAT_BYTES;
        const char* Al = smem + stage * STAGE_BYTES + 1 * MAT_BYTES;
        const char* Bh = smem + stage * STAGE_BYTES + 2 * MAT_BYTES;
        const char* Bl = smem + stage * STAGE_BYTES + 3 * MAT_BYTES;
#pragma unroll
        for (int ks = 0; ks < 2; ks++) {
            const int kb = ks * 32 + t * 4;
            uint32_t afh[4][4], afl[4][4];
#pragma unroll
            for (int ma = 0; ma < 4; ma++) {
                int ro = (wm + 16 * ma + g) * ROWB + kb;
                afh[ma][0] = *(const uint32_t*)(Ah + ro);
                afh[ma][1] = *(const uint32_t*)(Ah + ro + 8 * ROWB);
                afh[ma][2] = *(const uint32_t*)(Ah + ro + 16);
                afh[ma][3] = *(const uint32_t*)(Ah + ro + 8 * ROWB + 16);
                afl[ma][0] = *(const uint32_t*)(Al + ro);
                afl[ma][1] = *(const uint32_t*)(Al + ro + 8 * ROWB);
                afl[ma][2] = *(const uint32_t*)(Al + ro + 16);
                afl[ma][3] = *(const uint32_t*)(Al + ro + 8 * ROWB + 16);
            }
            uint32_t bfh[4][2], bfl[4][2];
#pragma unroll
            for (int na = 0; na < 4; na++) {
                int ro = (wn + 8 * na + g) * ROWB + kb;
                bfh[na][0] = *(const uint32_t*)(Bh + ro);
                bfh[na][1] = *(const uint32_t*)(Bh + ro + 16);
                bfl[na][0] = *(const uint32_t*)(Bl + ro);
                bfl[na][1] = *(const uint32_t*)(Bl + ro + 16);
            }
#pragma unroll
            for (int ma = 0; ma < 4; ma++)
#pragma unroll
                for (int na = 0; na < 4; na++)
                    mma_bf16(acc[ma][na], afh[ma], bfh[na]);
#pragma unroll
            for (int ma = 0; ma < 4; ma++)
#pragma unroll
                for (int na = 0; na < 4; na++)
                    mma_bf16(acc[ma][na], afh[ma], bfl[na]);
#pragma unroll
            for (int ma = 0; ma < 4; ma++)
#pragma unroll
                for (int na = 0; na < 4; na++)
                    mma_bf16(acc[ma][na], afl[ma], bfh[na]);
        }
    };

    ldg_chunk(0);
    sts_chunk(0);
    for (int c = 0; c < NC; c++) {
        __syncthreads();
        if (c + 1 < NC) ldg_chunk((c + 1) * BK);
        compute(c & 1);
        if (c + 1 < NC) sts_chunk((c + 1) & 1);
    }

#pragma unroll
    for (int na = 0; na < 4; na++) {
        const int f0 = col0 + wn + 8 * na + 2 * t;
        const float b0 = bias[f0];
        const float b1 = bias[f0 + 1];
        if (MODE == 0) {
            int h     = f0 / 192;
            int rem   = f0 - 192 * h;
            int which = rem >> 6;
            int dd    = rem & 63;
            float* dst = (which == 0) ? g_q : ((which == 1) ? g_k : g_v);
            float mul  = (which == 0) ? 0.125f : 1.0f;
#pragma unroll
            for (int ma = 0; ma < 4; ma++) {
                const float* d4 = acc[ma][na];
                int tb = row0 + wm + 16 * ma + g;
                {
                    int tt = tb >> 1, bb = tb & 1;
                    *(float2*)(dst + ((size_t)(bb * HH + h) * TQ + tt) * DD + dd) =
                        make_float2((d4[0] + b0) * mul, (d4[1] + b1) * mul);
                }
                {
                    int tb2 = tb + 8;
                    int tt = tb2 >> 1, bb = tb2 & 1;
                    *(float2*)(dst + ((size_t)(bb * HH + h) * TQ + tt) * DD + dd) =
                        make_float2((d4[2] + b0) * mul, (d4[3] + b1) * mul);
                }
            }
        } else {
#pragma unroll
            for (int ma = 0; ma < 4; ma++) {
                const float* d4 = acc[ma][na];
                int r = row0 + wm + 16 * ma + g;
                *(float2*)(Cout + (size_t)r * EE + f0) =
                    make_float2(d4[0] + b0, d4[1] + b1);
                *(float2*)(Cout + (size_t)(r + 8) * EE + f0) =
                    make_float2(d4[2] + b0, d4[3] + b1);
            }
        }
    }
}

// ============================================================================
// Flash attention on tensor cores (mma.sync bf16x3, d=64)
// CTA: 128 query rows of one (b,h); 8 warps x 16 rows; KV tiles of 64.
// QK: 3-pass bf16 from smem (ldmatrix). Softmax fp32 in registers.
// PV: P fragments straight from S accumulators (register split), V via
// ldmatrix.trans, 3-pass. Row state (m,l) in fp32.
// ============================================================================
#define AT_ROWB 144                      // 64 bf16 + 16B pad
#define AQ_H 0
#define AQ_L (128 * AT_ROWB)             // 18432
#define AK_H (2 * 128 * AT_ROWB)         // 36864
#define AK_L (AK_H + 64 * AT_ROWB)
#define AV_H (AK_H + 2 * 64 * AT_ROWB)
#define AV_L (AK_H + 3 * 64 * AT_ROWB)
#define ATTN_SMEM (AK_H + 4 * 64 * AT_ROWB)   // 73728

__global__ __launch_bounds__(256, 1)
void attn_mma_kernel()
{
    extern __shared__ char sm[];
    const uint32_t sb = smem_u32(sm);

    const int tid  = threadIdx.x;
    const int wid  = tid >> 5;
    const int lane = tid & 31;
    const int g    = lane >> 2;
    const int t    = lane & 3;

    const int bh = blockIdx.y;
    const int b  = bh >> 4;
    const int h  = bh & 15;
    const size_t base = (size_t)bh * TQ * DD;
    const int t0 = blockIdx.x * 128;

    // ---- stage Q tile (128x64) as bf16 hi/lo ----
#pragma unroll
    for (int p = 0; p < 8; p++) {
        int id = tid + p * 256;
        int r  = id >> 4;
        int cg = id & 15;
        float4 v = *(const float4*)(g_q + base + (size_t)(t0 + r) * DD + cg * 4);
        uint32_t h0, l0, h1, l1;
        split2(v.x, v.y, h0, l0);
        split2(v.z, v.w, h1, l1);
        *(uint2*)(sm + AQ_H + r * AT_ROWB + cg * 8) = make_uint2(h0, h1);
        *(uint2*)(sm + AQ_L + r * AT_ROWB + cg * 8) = make_uint2(l0, l1);
    }
    __syncthreads();

    // ---- Q fragments (persistent in registers) ----
    const int m0 = wid * 16;
    uint32_t qh[4][4], ql[4][4];
    {
        int row  = m0 + (lane & 15);
        int half = lane >> 4;
#pragma unroll
        for (int ks = 0; ks < 4; ks++) {
            uint32_t a = sb + AQ_H + row * AT_ROWB + ks * 32 + half * 16;
            LDSM_X4(qh[ks][0], qh[ks][1], qh[ks][2], qh[ks][3], a);
            a = sb + AQ_L + row * AT_ROWB + ks * 32 + half * 16;
            LDSM_X4(ql[ks][0], ql[ks][1], ql[ks][2], ql[ks][3], a);
        }
    }

    // lane address components for B-fragment ldmatrix
    const int rK = (lane & 7) + ((lane >> 4) & 1) * 8;   // QK: row-in-16, col sel by bit3
    const int cK = ((lane >> 3) & 1) * 16;
    const int rV = (lane & 7) + ((lane >> 3) & 1) * 8;   // PV(trans): row by bit3, col by bit4
    const int cV = ((lane >> 4) & 1) * 16;

    float O[8][4];
#pragma unroll
    for (int j = 0; j < 8; j++)
#pragma unroll
        for (int k = 0; k < 4; k++) O[j][k] = 0.0f;
    float mrow0 = -1e30f, mrow1 = -1e30f, lrow0 = 0.0f, lrow1 = 0.0f;

    for (int st = 0; st < TQ; st += 64) {
        __syncthreads();   // previous tile's ldmatrix reads done

        // ---- load K/V tile (64x64 fp32 each), split, store ----
#pragma unroll
        for (int p = 0; p < 4; p++) {
            int id = tid + p * 256;
            int r  = id >> 4;
            int cg = id & 15;
            float4 kv = *(const float4*)(g_k + base + (size_t)(st + r) * DD + cg * 4);
            uint32_t h0, l0, h1, l1;
            split2(kv.x, kv.y, h0, l0);
            split2(kv.z, kv.w, h1, l1);
            *(uint2*)(sm + AK_H + r * AT_ROWB + cg * 8) = make_uint2(h0, h1);
            *(uint2*)(sm + AK_L + r * AT_ROWB + cg * 8) = make_uint2(l0, l1);
            float4 vv = *(const float4*)(g_v + base + (size_t)(st + r) * DD + cg * 4);
            split2(vv.x, vv.y, h0, l0);
            split2(vv.z, vv.w, h1, l1);
            *(uint2*)(sm + AV_H + r * AT_ROWB + cg * 8) = make_uint2(h0, h1);
            *(uint2*)(sm + AV_L + r * AT_ROWB + cg * 8) = make_uint2(l0, l1);
        }
        __syncthreads();

        // ---- S = Q K^T : 16 x 64 per warp ----
        float S[8][4];
#pragma unroll
        for (int j = 0; j < 8; j++)
#pragma unroll
            for (int k = 0; k < 4; k++) S[j][k] = 0.0f;

#pragma unroll
        for (int ks = 0; ks < 4; ks++) {
            uint32_t bh_[8][2], bl_[8][2];
#pragma unroll
            for (int jj = 0; jj < 4; jj++) {
                uint32_t a = sb + AK_H + (16 * jj + rK) * AT_ROWB + ks * 32 + cK;
                LDSM_X4(bh_[2 * jj][0], bh_[2 * jj][1], bh_[2 * jj + 1][0], bh_[2 * jj + 1][1], a);
                a = sb + AK_L + (16 * jj + rK) * AT_ROWB + ks * 32 + cK;
                LDSM_X4(bl_[2 * jj][0], bl_[2 * jj][1], bl_[2 * jj + 1][0], bl_[2 * jj + 1][1], a);
            }
#pragma unroll
            for (int j = 0; j < 8; j++) mma_bf16(S[j], qh[ks], bh_[j]);
#pragma unroll
            for (int j = 0; j < 8; j++) mma_bf16(S[j], qh[ks], bl_[j]);
#pragma unroll
            for (int j = 0; j < 8; j++) mma_bf16(S[j], ql[ks], bh_[j]);
        }

        // ---- online softmax (rows g and g+8; cols across t-quads) ----
        float mx0 = -1e30f, mx1 = -1e30f;
#pragma unroll
        for (int j = 0; j < 8; j++) {
            mx0 = fmaxf(mx0, fmaxf(S[j][0], S[j][1]));
            mx1 = fmaxf(mx1, fmaxf(S[j][2], S[j][3]));
        }
        mx0 = fmaxf(mx0, __shfl_xor_sync(0xffffffffu, mx0, 1));
        mx0 = fmaxf(mx0, __shfl_xor_sync(0xffffffffu, mx0, 2));
        mx1 = fmaxf(mx1, __shfl_xor_sync(0xffffffffu, mx1, 1));
        mx1 = fmaxf(mx1, __shfl_xor_sync(0xffffffffu, mx1, 2));
        float mn0 = fmaxf(mrow0, mx0), mn1 = fmaxf(mrow1, mx1);
        float sc0 = __expf(mrow0 - mn0), sc1 = __expf(mrow1 - mn1);
        float s0 = 0.0f, s1 = 0.0f;
#pragma unroll
        for (int j = 0; j < 8; j++) {
            S[j][0] = __expf(S[j][0] - mn0);
            S[j][1] = __expf(S[j][1] - mn0);
            S[j][2] = __expf(S[j][2] - mn1);
            S[j][3] = __expf(S[j][3] - mn1);
            s0 += S[j][0] + S[j][1];
            s1 += S[j][2] + S[j][3];
        }
        s0 += __shfl_xor_sync(0xffffffffu, s0, 1);
        s0 += __shfl_xor_sync(0xffffffffu, s0, 2);
        s1 += __shfl_xor_sync(0xffffffffu, s1, 1);
        s1 += __shfl_xor_sync(0xffffffffu, s1, 2);
        lrow0 = lrow0 * sc0 + s0;
        lrow1 = lrow1 * sc1 + s1;
        mrow0 = mn0;
        mrow1 = mn1;
#pragma unroll
        for (int j = 0; j < 8; j++) {
            O[j][0] *= sc0; O[j][1] *= sc0;
            O[j][2] *= sc1; O[j][3] *= sc1;
        }

        // ---- P fragments from S accumulators (register split) ----
        uint32_t ph[4][4], pl[4][4];
#pragma unroll
        for (int kk = 0; kk < 4; kk++) {
            split2(S[2 * kk][0],     S[2 * kk][1],     ph[kk][0], pl[kk][0]);
            split2(S[2 * kk][2],     S[2 * kk][3],     ph[kk][1], pl[kk][1]);
            split2(S[2 * kk + 1][0], S[2 * kk + 1][1], ph[kk][2], pl[kk][2]);
            split2(S[2 * kk + 1][2], S[2 * kk + 1][3], ph[kk][3], pl[kk][3]);
        }

        // ---- O += P V : 16 x 64 per warp, k = 64 (s) ----
#pragma unroll
        for (int kk = 0; kk < 4; kk++) {
            uint32_t vh_[8][2], vl_[8][2];
#pragma unroll
            for (int jj = 0; jj < 4; jj++) {
                uint32_t a = sb + AV_H + (kk * 16 + rV) * AT_ROWB + jj * 32 + cV;
                LDSM_X4_T(vh_[2 * jj][0], vh_[2 * jj][1], vh_[2 * jj + 1][0], vh_[2 * jj + 1][1], a);
                a = sb + AV_L + (kk * 16 + rV) * AT_ROWB + jj * 32 + cV;
                LDSM_X4_T(vl_[2 * jj][0], vl_[2 * jj][1], vl_[2 * jj + 1][0], vl_[2 * jj + 1][1], a);
            }
#pragma unroll
            for (int j = 0; j < 8; j++) mma_bf16(O[j], ph[kk], vh_[j]);
#pragma unroll
            for (int j = 0; j < 8; j++) mma_bf16(O[j], ph[kk], vl_[j]);
#pragma unroll
            for (int j = 0; j < 8; j++) mma_bf16(O[j], pl[kk], vh_[j]);
        }
    }

    // ---- epilogue: O / l -> g_ctx [TB, EE] ----
    float inv0 = 1.0f / lrow0, inv1 = 1.0f / lrow1;
    int qr0 = t0 + m0 + g;
    int qr1 = qr0 + 8;
#pragma unroll
    for (int j = 0; j < 8; j++) {
        int col = h * 64 + 8 * j + 2 * t;
        *(float2*)(g_ctx + (size_t)(qr0 * BB + b) * EE + col) =
            make_float2(O[j][0] * inv0, O[j][1] * inv0);
        *(float2*)(g_ctx + (size_t)(qr1 * BB + b) * EE + col) =
            make_float2(O[j][2] * inv1, O[j][3] * inv1);
    }
}

// ============================================================================
// Launch
// ============================================================================
extern "C" void kernel_launch(void* const* d_in, const int* in_sizes, int n_in,
                              void* d_out, int out_size)
{
    const float* query = (const float*)d_in[0];
    const float* w_in  = (const float*)d_in[1];
    const float* b_in  = (const float*)d_in[2];
    const float* w_out = (const float*)d_in[3];
    const float* b_out = (const float*)d_in[4];
    float* out = (float*)d_out;

    cudaFuncSetAttribute(attn_mma_kernel, cudaFuncAttributeMaxDynamicSharedMemorySize, ATTN_SMEM);
    cudaFuncSetAttribute(mma_gemm_kernel<0>, cudaFuncAttributeMaxDynamicSharedMemorySize, GEMM_SMEM);
    cudaFuncSetAttribute(mma_gemm_kernel<1>, cudaFuncAttributeMaxDynamicSharedMemorySize, GEMM_SMEM);

    // 1) QKV projection (mma.sync bf16x3) + bias + scale + scatter
    mma_gemm_kernel<0><<<dim3(FF / 128, TB / 128), 256, GEMM_SMEM>>>(query, w_in, b_in, nullptr);
    // 2) Flash attention (mma.sync bf16x3) -> ctx [TB, EE]
    attn_mma_kernel<<<dim3(TQ / 128, BB * HH), 256, ATTN_SMEM>>>();
    // 3) Output projection (mma.sync bf16x3) + bias -> d_out
    mma_gemm_kernel<1><<<dim3(EE / 128, TB / 128), 256, GEMM_SMEM>>>(nullptr, w_out, b_out, out);
}

// round 6
// speedup vs baseline: 2.9458x; 1.3767x over previous
#include <cuda_runtime.h>
#include <cuda_bf16.h>
#include <math.h>
#include <cstdint>

// Problem constants
#define TQ 2048
#define BB 2
#define EE 1024
#define HH 16
#define DD 64
#define TB 4096          // TQ*BB
#define FF 3072          // 3*EE

#define QSCALE (0.125f * 1.44269504088896f)   // d^-0.5 * log2(e)  (softmax uses ex2)

// Scratch (allocation-free rule: __device__ globals) — all pre-split bf16 hi/lo
__device__ __nv_bfloat16 g_qryh[(size_t)TB * EE], g_qryl[(size_t)TB * EE];
__device__ __nv_bfloat16 g_wih[(size_t)FF * EE],  g_wil[(size_t)FF * EE];
__device__ __nv_bfloat16 g_woh[(size_t)EE * EE],  g_wol[(size_t)EE * EE];
__device__ __nv_bfloat16 g_qh[(size_t)BB * HH * TQ * DD], g_ql[(size_t)BB * HH * TQ * DD];
__device__ __nv_bfloat16 g_kh[(size_t)BB * HH * TQ * DD], g_kl[(size_t)BB * HH * TQ * DD];
__device__ __nv_bfloat16 g_vh[(size_t)BB * HH * TQ * DD], g_vl[(size_t)BB * HH * TQ * DD];
__device__ __nv_bfloat16 g_ctxh[(size_t)TB * EE], g_ctxl[(size_t)TB * EE];

// ============================================================================
// helpers
// ============================================================================
__device__ __forceinline__ uint32_t smem_u32(const void* p) {
    uint32_t a;
    asm("{ .reg .u64 t; cvta.to.shared.u64 t, %1; cvt.u32.u64 %0, t; }" : "=r"(a) : "l"(p));
    return a;
}
__device__ __forceinline__ uint32_t pack2(__nv_bfloat16 a, __nv_bfloat16 b) {
    uint16_t ua = *(uint16_t*)&a, ub = *(uint16_t*)&b;
    return (uint32_t)ua | ((uint32_t)ub << 16);
}
__device__ __forceinline__ void split2(float x, float y, uint32_t& hi, uint32_t& lo) {
    __nv_bfloat16 hx = __float2bfloat16(x), hy = __float2bfloat16(y);
    __nv_bfloat16 lx = __float2bfloat16(x - __bfloat162float(hx));
    __nv_bfloat16 ly = __float2bfloat16(y - __bfloat162float(hy));
    hi = pack2(hx, hy);
    lo = pack2(lx, ly);
}
__device__ __forceinline__ float ex2f(float x) {
    float y;
    asm("ex2.approx.f32 %0, %1;" : "=f"(y) : "f"(x));
    return y;
}
__device__ __forceinline__ void mma_bf16(float* d, const uint32_t* a, const uint32_t* b) {
    asm volatile(
        "mma.sync.aligned.m16n8k16.row.col.f32.bf16.bf16.f32 "
        "{%0,%1,%2,%3}, {%4,%5,%6,%7}, {%8,%9}, {%0,%1,%2,%3};"
        : "+f"(d[0]), "+f"(d[1]), "+f"(d[2]), "+f"(d[3])
        : "r"(a[0]), "r"(a[1]), "r"(a[2]), "r"(a[3]), "r"(b[0]), "r"(b[1]));
}
#define LDSM_X4(R0,R1,R2,R3,ADDR) \
    asm volatile("ldmatrix.sync.aligned.m8n8.x4.shared.b16 {%0,%1,%2,%3}, [%4];" \
        : "=r"(R0), "=r"(R1), "=r"(R2), "=r"(R3) : "r"(ADDR))
#define LDSM_X4_T(R0,R1,R2,R3,ADDR) \
    asm volatile("ldmatrix.sync.aligned.m8n8.x4.trans.shared.b16 {%0,%1,%2,%3}, [%4];" \
        : "=r"(R0), "=r"(R1), "=r"(R2), "=r"(R3) : "r"(ADDR))
#define CP16(SM, GP) \
    asm volatile("cp.async.cg.shared.global [%0], [%1], 16;" :: "r"(SM), "l"(GP) : "memory")
#define CP_COMMIT() asm volatile("cp.async.commit_group;" ::: "memory")
#define CP_WAIT(N)  asm volatile("cp.async.wait_group %0;" :: "n"(N) : "memory")

// ============================================================================
// fp32 -> bf16 hi/lo split (elementwise, HBM-bound)
// ============================================================================
__global__ void split_kernel(const float* __restrict__ src,
                             __nv_bfloat16* __restrict__ hi,
                             __nv_bfloat16* __restrict__ lo, int n4)
{
    int i = blockIdx.x * blockDim.x + threadIdx.x;
    if (i < n4) {
        float4 v = ((const float4*)src)[i];
        uint32_t h0, l0, h1, l1;
        split2(v.x, v.y, h0, l0);
        split2(v.z, v.w, h1, l1);
        ((uint2*)hi)[i] = make_uint2(h0, h1);
        ((uint2*)lo)[i] = make_uint2(l0, l1);
    }
}

// ============================================================================
// GEMM v2: C[M,N] = A[M,K]*W[N,K]^T + bias, inputs pre-split bf16 hi/lo.
// 128x128 CTA tile, 512 threads (16 warps, warp tile 32x32), K-chunk 32,
// 3-stage cp.async pipeline, ldmatrix + XOR swizzle, bf16x3.
// MODE 0: scatter into q/k/v hi/lo (q scaled). MODE 1: fp32 out + bias.
// ============================================================================
#define GBK 32
#define GNC (EE / GBK)          // 32 chunks
#define GS_A_H 0
#define GS_A_L 8192
#define GS_B_H 16384
#define GS_B_L 24576
#define G_STAGE_BYTES 32768
#define GEMM_SMEM2 (3 * G_STAGE_BYTES)   // 98304

template <int MODE>
__global__ __launch_bounds__(512, 1)
void mma_gemm2(const __nv_bfloat16* __restrict__ Agh, const __nv_bfloat16* __restrict__ Agl,
               const __nv_bfloat16* __restrict__ Bgh, const __nv_bfloat16* __restrict__ Bgl,
               const float* __restrict__ bias, float* __restrict__ Cout)
{
    extern __shared__ char smem[];
    const uint32_t sb = smem_u32(smem);

    const int tid  = threadIdx.x;
    const int wid  = tid >> 5;
    const int lane = tid & 31;
    const int g    = lane >> 2;
    const int t    = lane & 3;
    const int wm   = (wid >> 2) << 5;   // 0..96
    const int wn   = (wid & 3) << 5;    // 0..96
    const int row0 = blockIdx.y * 128;
    const int col0 = blockIdx.x * 128;
    const int rK   = (lane & 7) + ((lane >> 4) & 1) * 8;
    const int cKb  = (lane >> 3) & 1;

    float acc[2][4][4];
#pragma unroll
    for (int i = 0; i < 2; i++)
#pragma unroll
        for (int j = 0; j < 4; j++)
#pragma unroll
            for (int k = 0; k < 4; k++) acc[i][j][k] = 0.0f;

    // copy lane map: 128 rows x 4 x 16B groups per matrix
    const int cr = tid >> 2;
    const int cg = tid & 3;
    const uint32_t s_off = (uint32_t)cr * 64 + (uint32_t)((cg ^ ((cr >> 1) & 3)) << 4);
    const size_t gA0 = (size_t)(row0 + cr) * EE + cg * 8;
    const size_t gB0 = (size_t)(col0 + cr) * EE + cg * 8;

    auto issue = [&](int c) {
        uint32_t st = sb + (uint32_t)(c % 3) * G_STAGE_BYTES;
        size_t ka = gA0 + (size_t)c * GBK;
        size_t kb = gB0 + (size_t)c * GBK;
        CP16(st + GS_A_H + s_off, Agh + ka);
        CP16(st + GS_A_L + s_off, Agl + ka);
        CP16(st + GS_B_H + s_off, Bgh + kb);
        CP16(st + GS_B_L + s_off, Bgl + kb);
        CP_COMMIT();
    };

    auto compute = [&](int stage) {
        uint32_t base = sb + (uint32_t)stage * G_STAGE_BYTES;
#pragma unroll
        for (int ks = 0; ks < 2; ks++) {
            uint32_t ah[2][4], al[2][4];
#pragma unroll
            for (int ma = 0; ma < 2; ma++) {
                int row  = wm + 16 * ma + (lane & 15);
                int cgrp = ks * 2 + (lane >> 4);
                uint32_t ad = base + GS_A_H + row * 64 + ((cgrp ^ ((row >> 1) & 3)) << 4);
                LDSM_X4(ah[ma][0], ah[ma][1], ah[ma][2], ah[ma][3], ad);
                LDSM_X4(al[ma][0], al[ma][1], al[ma][2], al[ma][3], ad + 8192);
            }
            uint32_t bh2[4][2], bl2[4][2];
#pragma unroll
            for (int jj = 0; jj < 2; jj++) {
                int row  = wn + 16 * jj + rK;
                int cgrp = ks * 2 + cKb;
                uint32_t ad = base + GS_B_H + row * 64 + ((cgrp ^ ((row >> 1) & 3)) << 4);
                LDSM_X4(bh2[2 * jj][0], bh2[2 * jj][1], bh2[2 * jj + 1][0], bh2[2 * jj + 1][1], ad);
                LDSM_X4(bl2[2 * jj][0], bl2[2 * jj][1], bl2[2 * jj + 1][0], bl2[2 * jj + 1][1], ad + 8192);
            }
#pragma unroll
            for (int ma = 0; ma < 2; ma++)
#pragma unroll
                for (int na = 0; na < 4; na++) mma_bf16(acc[ma][na], ah[ma], bh2[na]);
#pragma unroll
            for (int ma = 0; ma < 2; ma++)
#pragma unroll
                for (int na = 0; na < 4; na++) mma_bf16(acc[ma][na], ah[ma], bl2[na]);
#pragma unroll
            for (int ma = 0; ma < 2; ma++)
#pragma unroll
                for (int na = 0; na < 4; na++) mma_bf16(acc[ma][na], al[ma], bh2[na]);
        }
    };

    issue(0);
    issue(1);
    for (int c = 0; c < GNC; c++) {
        if (c + 2 < GNC) { CP_WAIT(1); } else { CP_WAIT(0); }
        __syncthreads();
        if (c + 2 < GNC) issue(c + 2);
        compute(c % 3);
    }

    // ---- epilogue ----
#pragma unroll
    for (int na = 0; na < 4; na++) {
        const int f0 = col0 + wn + 8 * na + 2 * t;
        const float b0 = bias[f0];
        const float b1 = bias[f0 + 1];
        if (MODE == 0) {
            int h     = f0 / 192;
            int rem   = f0 - 192 * h;
            int which = rem >> 6;
            int dd    = rem & 63;
            __nv_bfloat16* dh = (which == 0) ? g_qh : ((which == 1) ? g_kh : g_vh);
            __nv_bfloat16* dl = (which == 0) ? g_ql : ((which == 1) ? g_kl : g_vl);
            float mul = (which == 0) ? QSCALE : 1.0f;
#pragma unroll
            for (int ma = 0; ma < 2; ma++) {
                const float* d4 = acc[ma][na];
                int tb = row0 + wm + 16 * ma + g;
#pragma unroll
                for (int hh = 0; hh < 2; hh++) {
                    int tbx = tb + 8 * hh;
                    int tt = tbx >> 1, bb = tbx & 1;
                    size_t off = ((size_t)(bb * HH + h) * TQ + tt) * DD + dd;
                    uint32_t hi, lo;
                    split2((d4[2 * hh] + b0) * mul, (d4[2 * hh + 1] + b1) * mul, hi, lo);
                    *(uint32_t*)(dh + off) = hi;
                    *(uint32_t*)(dl + off) = lo;
                }
            }
        } else {
#pragma unroll
            for (int ma = 0; ma < 2; ma++) {
                const float* d4 = acc[ma][na];
                int r = row0 + wm + 16 * ma + g;
                *(float2*)(Cout + (size_t)r * EE + f0) = make_float2(d4[0] + b0, d4[1] + b1);
                *(float2*)(Cout + (size_t)(r + 8) * EE + f0) = make_float2(d4[2] + b0, d4[3] + b1);
            }
        }
    }
}

// ============================================================================
// Flash attention v2 (mma.sync bf16x3), K/V pre-split, cp.async double-buffer.
// CTA: 128 q-rows of one (b,h), 8 warps x 16 rows, KV tiles of 64.
// ============================================================================
#define AQ_H2 0
#define AQ_L2 16384
#define AKV0  32768                 // per stage: KH 0, KL 8192, VH 16384, VL 24576
#define AKV_STAGE 32768
#define ATTN_SMEM2 (AKV0 + 2 * AKV_STAGE)    // 98304

__global__ __launch_bounds__(256, 1)
void attn_mma2()
{
    extern __shared__ char sm[];
    const uint32_t sb = smem_u32(sm);

    const int tid  = threadIdx.x;
    const int wid  = tid >> 5;
    const int lane = tid & 31;
    const int g    = lane >> 2;
    const int t    = lane & 3;

    const int bh = blockIdx.y;
    const int b  = bh >> 4;
    const int h  = bh & 15;
    const size_t base = (size_t)bh * TQ * DD;
    const int t0 = blockIdx.x * 128;
    const int m0 = wid * 16;

    const int rK  = (lane & 7) + ((lane >> 4) & 1) * 8;
    const int cKb = (lane >> 3) & 1;
    const int rV  = (lane & 7) + ((lane >> 3) & 1) * 8;
    const int cVb = (lane >> 4) & 1;

    // copy lane map: rows of 128B, 8 x 16B groups, swizzle c ^ (r&7)
    auto issueQ = [&]() {
#pragma unroll
        for (int p = 0; p < 4; p++) {
            int id = tid + p * 256;
            int r = id >> 3, cgp = id & 7;
            uint32_t so = (uint32_t)r * 128 + ((cgp ^ (r & 7)) << 4);
            size_t go = base + (size_t)(t0 + r) * DD + cgp * 8;
            CP16(sb + AQ_H2 + so, g_qh + go);
            CP16(sb + AQ_L2 + so, g_ql + go);
        }
        CP_COMMIT();
    };
    auto issueKV = [&](int st, int buf) {
        uint32_t kvb = sb + AKV0 + (uint32_t)buf * AKV_STAGE;
#pragma unroll
        for (int p = 0; p < 2; p++) {
            int id = tid + p * 256;
            int r = id >> 3, cgp = id & 7;
            uint32_t so = (uint32_t)r * 128 + ((cgp ^ (r & 7)) << 4);
            size_t go = base + (size_t)(st + r) * DD + cgp * 8;
            CP16(kvb + so,         g_kh + go);
            CP16(kvb + 8192 + so,  g_kl + go);
            CP16(kvb + 16384 + so, g_vh + go);
            CP16(kvb + 24576 + so, g_vl + go);
        }
        CP_COMMIT();
    };

    issueQ();
    issueKV(0, 0);
    CP_WAIT(0);
    __syncthreads();

    // ---- Q fragments (persistent) ----
    uint32_t qh[4][4], ql[4][4];
    {
        int row = m0 + (lane & 15);
#pragma unroll
        for (int ks = 0; ks < 4; ks++) {
            int cgrp = ks * 2 + (lane >> 4);
            uint32_t a = sb + AQ_H2 + row * 128 + ((cgrp ^ (row & 7)) << 4);
            LDSM_X4(qh[ks][0], qh[ks][1], qh[ks][2], qh[ks][3], a);
            LDSM_X4(ql[ks][0], ql[ks][1], ql[ks][2], ql[ks][3], a + 16384);
        }
    }

    float O[8][4];
#pragma unroll
    for (int j = 0; j < 8; j++)
#pragma unroll
        for (int k = 0; k < 4; k++) O[j][k] = 0.0f;
    float mrow0 = -1e30f, mrow1 = -1e30f, lrow0 = 0.0f, lrow1 = 0.0f;

    for (int i = 0; i < TQ / 64; i++) {
        if (i > 0) {
            CP_WAIT(0);
            __syncthreads();     // tile i visible; all warps done with buf (i+1)&1
        }
        if (i + 1 < TQ / 64) issueKV((i + 1) * 64, (i + 1) & 1);

        uint32_t kvb = sb + AKV0 + (uint32_t)(i & 1) * AKV_STAGE;

        // ---- S = Q K^T ----
        float S[8][4];
#pragma unroll
        for (int j = 0; j < 8; j++)
#pragma unroll
            for (int k = 0; k < 4; k++) S[j][k] = 0.0f;

#pragma unroll
        for (int ks = 0; ks < 4; ks++) {
            uint32_t bh_[8][2], bl_[8][2];
#pragma unroll
            for (int jj = 0; jj < 4; jj++) {
                int row  = 16 * jj + rK;
                int cgrp = ks * 2 + cKb;
                uint32_t a = kvb + row * 128 + ((cgrp ^ (row & 7)) << 4);
                LDSM_X4(bh_[2 * jj][0], bh_[2 * jj][1], bh_[2 * jj + 1][0], bh_[2 * jj + 1][1], a);
                LDSM_X4(bl_[2 * jj][0], bl_[2 * jj][1], bl_[2 * jj + 1][0], bl_[2 * jj + 1][1], a + 8192);
            }
#pragma unroll
            for (int j = 0; j < 8; j++) mma_bf16(S[j], qh[ks], bh_[j]);
#pragma unroll
            for (int j = 0; j < 8; j++) mma_bf16(S[j], qh[ks], bl_[j]);
#pragma unroll
            for (int j = 0; j < 8; j++) mma_bf16(S[j], ql[ks], bh_[j]);
        }

        // ---- online softmax (base-2) ----
        float mx0 = -1e30f, mx1 = -1e30f;
#pragma unroll
        for (int j = 0; j < 8; j++) {
            mx0 = fmaxf(mx0, fmaxf(S[j][0], S[j][1]));
            mx1 = fmaxf(mx1, fmaxf(S[j][2], S[j][3]));
        }
        mx0 = fmaxf(mx0, __shfl_xor_sync(0xffffffffu, mx0, 1));
        mx0 = fmaxf(mx0, __shfl_xor_sync(0xffffffffu, mx0, 2));
        mx1 = fmaxf(mx1, __shfl_xor_sync(0xffffffffu, mx1, 1));
        mx1 = fmaxf(mx1, __shfl_xor_sync(0xffffffffu, mx1, 2));
        float mn0 = fmaxf(mrow0, mx0), mn1 = fmaxf(mrow1, mx1);
        float sc0 = ex2f(mrow0 - mn0), sc1 = ex2f(mrow1 - mn1);
        float s0 = 0.0f, s1 = 0.0f;
#pragma unroll
        for (int j = 0; j < 8; j++) {
            S[j][0] = ex2f(S[j][0] - mn0);
            S[j][1] = ex2f(S[j][1] - mn0);
            S[j][2] = ex2f(S[j][2] - mn1);
            S[j][3] = ex2f(S[j][3] - mn1);
            s0 += S[j][0] + S[j][1];
            s1 += S[j][2] + S[j][3];
        }
        s0 += __shfl_xor_sync(0xffffffffu, s0, 1);
        s0 += __shfl_xor_sync(0xffffffffu, s0, 2);
        s1 += __shfl_xor_sync(0xffffffffu, s1, 1);
        s1 += __shfl_xor_sync(0xffffffffu, s1, 2);
        lrow0 = lrow0 * sc0 + s0;
        lrow1 = lrow1 * sc1 + s1;
        mrow0 = mn0;
        mrow1 = mn1;
#pragma unroll
        for (int j = 0; j < 8; j++) {
            O[j][0] *= sc0; O[j][1] *= sc0;
            O[j][2] *= sc1; O[j][3] *= sc1;
        }

        // ---- P fragments from S accumulators ----
        uint32_t ph[4][4], pl[4][4];
#pragma unroll
        for (int kk = 0; kk < 4; kk++) {
            split2(S[2 * kk][0],     S[2 * kk][1],     ph[kk][0], pl[kk][0]);
            split2(S[2 * kk][2],     S[2 * kk][3],     ph[kk][1], pl[kk][1]);
            split2(S[2 * kk + 1][0], S[2 * kk + 1][1], ph[kk][2], pl[kk][2]);
            split2(S[2 * kk + 1][2], S[2 * kk + 1][3], ph[kk][3], pl[kk][3]);
        }

        // ---- O += P V ----
#pragma unroll
        for (int kk = 0; kk < 4; kk++) {
            uint32_t vh_[8][2], vl_[8][2];
#pragma unroll
            for (int jj = 0; jj < 4; jj++) {
                int row  = kk * 16 + rV;
                int cgrp = jj * 2 + cVb;
                uint32_t a = kvb + 16384 + row * 128 + ((cgrp ^ (row & 7)) << 4);
                LDSM_X4_T(vh_[2 * jj][0], vh_[2 * jj][1], vh_[2 * jj + 1][0], vh_[2 * jj + 1][1], a);
                LDSM_X4_T(vl_[2 * jj][0], vl_[2 * jj][1], vl_[2 * jj + 1][0], vl_[2 * jj + 1][1], a + 8192);
            }
#pragma unroll
            for (int j = 0; j < 8; j++) mma_bf16(O[j], ph[kk], vh_[j]);
#pragma unroll
            for (int j = 0; j < 8; j++) mma_bf16(O[j], ph[kk], vl_[j]);
#pragma unroll
            for (int j = 0; j < 8; j++) mma_bf16(O[j], pl[kk], vh_[j]);
        }
    }

    // ---- epilogue: ctx hi/lo bf16, layout [TB, EE] ----
    float inv0 = 1.0f / lrow0, inv1 = 1.0f / lrow1;
    int qr0 = t0 + m0 + g;
    int qr1 = qr0 + 8;
#pragma unroll
    for (int j = 0; j < 8; j++) {
        int col = h * 64 + 8 * j + 2 * t;
        uint32_t hi, lo;
        size_t o0 = (size_t)(qr0 * BB + b) * EE + col;
        split2(O[j][0] * inv0, O[j][1] * inv0, hi, lo);
        *(uint32_t*)(g_ctxh + o0) = hi;
        *(uint32_t*)(g_ctxl + o0) = lo;
        size_t o1 = (size_t)(qr1 * BB + b) * EE + col;
        split2(O[j][2] * inv1, O[j][3] * inv1, hi, lo);
        *(uint32_t*)(g_ctxh + o1) = hi;
        *(uint32_t*)(g_ctxl + o1) = lo;
    }
}

// ============================================================================
// Launch
// ============================================================================
extern "C" void kernel_launch(void* const* d_in, const int* in_sizes, int n_in,
                              void* d_out, int out_size)
{
    const float* query = (const float*)d_in[0];
    const float* w_in  = (const float*)d_in[1];
    const float* b_in  = (const float*)d_in[2];
    const float* w_out = (const float*)d_in[3];
    const float* b_out = (const float*)d_in[4];
    float* out = (float*)d_out;

    __nv_bfloat16 *p_qryh, *p_qryl, *p_wih, *p_wil, *p_woh, *p_wol;
    __nv_bfloat16 *p_ctxh, *p_ctxl;
    cudaGetSymbolAddress((void**)&p_qryh, g_qryh);
    cudaGetSymbolAddress((void**)&p_qryl, g_qryl);
    cudaGetSymbolAddress((void**)&p_wih,  g_wih);
    cudaGetSymbolAddress((void**)&p_wil,  g_wil);
    cudaGetSymbolAddress((void**)&p_woh,  g_woh);
    cudaGetSymbolAddress((void**)&p_wol,  g_wol);
    cudaGetSymbolAddress((void**)&p_ctxh, g_ctxh);
    cudaGetSymbolAddress((void**)&p_ctxl, g_ctxl);

    cudaFuncSetAttribute(mma_gemm2<0>, cudaFuncAttributeMaxDynamicSharedMemorySize, GEMM_SMEM2);
    cudaFuncSetAttribute(mma_gemm2<1>, cudaFuncAttributeMaxDynamicSharedMemorySize, GEMM_SMEM2);
    cudaFuncSetAttribute(attn_mma2, cudaFuncAttributeMaxDynamicSharedMemorySize, ATTN_SMEM2);

    // 0) pre-split inputs to bf16 hi/lo
    split_kernel<<<(TB * EE / 4 + 255) / 256, 256>>>(query, p_qryh, p_qryl, TB * EE / 4);
    split_kernel<<<(FF * EE / 4 + 255) / 256, 256>>>(w_in, p_wih, p_wil, FF * EE / 4);
    split_kernel<<<(EE * EE / 4 + 255) / 256, 256>>>(w_out, p_woh, p_wol, EE * EE / 4);

    // 1) QKV projection -> q/k/v hi/lo (q pre-scaled by d^-0.5*log2e)
    mma_gemm2<0><<<dim3(FF / 128, TB / 128), 512, GEMM_SMEM2>>>(p_qryh, p_qryl, p_wih, p_wil, b_in, nullptr);
    // 2) Flash attention -> ctx hi/lo
    attn_mma2<<<dim3(TQ / 128, BB * HH), 256, ATTN_SMEM2>>>();
    // 3) Output projection -> fp32 out
    mma_gemm2<1><<<dim3(EE / 128, TB / 128), 512, GEMM_SMEM2>>>(p_ctxh, p_ctxl, p_woh, p_wol, b_out, out);
}

// round 7
// speedup vs baseline: 3.9658x; 1.3463x over previous
#include <cuda_runtime.h>
#include <cuda_fp16.h>
#include <math.h>
#include <cstdint>

// Problem constants
#define TQ 2048
#define BB 2
#define EE 1024
#define HH 16
#define DD 64
#define TB 4096          // TQ*BB
#define FF 3072          // 3*EE

#define QSCALE (0.125f * 1.44269504088896f)   // d^-0.5 * log2(e)  (softmax uses ex2)

// Scratch (allocation-free rule: __device__ globals)
__device__ __half g_qry16[(size_t)TB * EE];                       // A for gemm0 (fp16)
__device__ __half g_wih[(size_t)FF * EE], g_wil[(size_t)FF * EE]; // W_in hi/lo
__device__ __half g_woh[(size_t)EE * EE], g_wol[(size_t)EE * EE]; // W_out hi/lo
__device__ __half g_q16[(size_t)BB * HH * TQ * DD];               // Q fp16 (pre-scaled)
__device__ __half g_kh[(size_t)BB * HH * TQ * DD], g_kl[(size_t)BB * HH * TQ * DD];
__device__ __half g_vh[(size_t)BB * HH * TQ * DD], g_vl[(size_t)BB * HH * TQ * DD];
__device__ __half g_ctx16[(size_t)TB * EE];                       // A for gemm1 (fp16)

// ============================================================================
// helpers
// ============================================================================
__device__ __forceinline__ uint32_t smem_u32(const void* p) {
    uint32_t a;
    asm("{ .reg .u64 t; cvta.to.shared.u64 t, %1; cvt.u32.u64 %0, t; }" : "=r"(a) : "l"(p));
    return a;
}
__device__ __forceinline__ uint32_t cvt2h(float x, float y) {
    __half2 h = __floats2half2_rn(x, y);
    return *(uint32_t*)&h;
}
// split (x,y) into packed fp16 hi and lo words (x in low half)
__device__ __forceinline__ void split2h(float x, float y, uint32_t& hi, uint32_t& lo) {
    __half hx = __float2half_rn(x), hy = __float2half_rn(y);
    float rx = x - __half2float(hx), ry = y - __half2float(hy);
    __half2 h = __halves2half2(hx, hy);
    hi = *(uint32_t*)&h;
    lo = cvt2h(rx, ry);
}
__device__ __forceinline__ float ex2f(float x) {
    float y;
    asm("ex2.approx.f32 %0, %1;" : "=f"(y) : "f"(x));
    return y;
}
__device__ __forceinline__ void mma_f16(float* d, const uint32_t* a, const uint32_t* b) {
    asm volatile(
        "mma.sync.aligned.m16n8k16.row.col.f32.f16.f16.f32 "
        "{%0,%1,%2,%3}, {%4,%5,%6,%7}, {%8,%9}, {%0,%1,%2,%3};"
        : "+f"(d[0]), "+f"(d[1]), "+f"(d[2]), "+f"(d[3])
        : "r"(a[0]), "r"(a[1]), "r"(a[2]), "r"(a[3]), "r"(b[0]), "r"(b[1]));
}
#define LDSM_X4(R0,R1,R2,R3,ADDR) \
    asm volatile("ldmatrix.sync.aligned.m8n8.x4.shared.b16 {%0,%1,%2,%3}, [%4];" \
        : "=r"(R0), "=r"(R1), "=r"(R2), "=r"(R3) : "r"(ADDR))
#define LDSM_X4_T(R0,R1,R2,R3,ADDR) \
    asm volatile("ldmatrix.sync.aligned.m8n8.x4.trans.shared.b16 {%0,%1,%2,%3}, [%4];" \
        : "=r"(R0), "=r"(R1), "=r"(R2), "=r"(R3) : "r"(ADDR))
#define CP16(SM, GP) \
    asm volatile("cp.async.cg.shared.global [%0], [%1], 16;" :: "r"(SM), "l"(GP) : "memory")
#define CP_COMMIT() asm volatile("cp.async.commit_group;" ::: "memory")
#define CP_WAIT(N)  asm volatile("cp.async.wait_group %0;" :: "n"(N) : "memory")

// ============================================================================
// elementwise converters (HBM-bound, one-time)
// ============================================================================
__global__ void split16_kernel(const float* __restrict__ src,
                               __half* __restrict__ hi, __half* __restrict__ lo, int n4)
{
    int i = blockIdx.x * blockDim.x + threadIdx.x;
    if (i < n4) {
        float4 v = ((const float4*)src)[i];
        uint32_t h0, l0, h1, l1;
        split2h(v.x, v.y, h0, l0);
        split2h(v.z, v.w, h1, l1);
        ((uint2*)hi)[i] = make_uint2(h0, h1);
        ((uint2*)lo)[i] = make_uint2(l0, l1);
    }
}
__global__ void cvt16_kernel(const float* __restrict__ src, __half* __restrict__ dst, int n4)
{
    int i = blockIdx.x * blockDim.x + threadIdx.x;
    if (i < n4) {
        float4 v = ((const float4*)src)[i];
        ((uint2*)dst)[i] = make_uint2(cvt2h(v.x, v.y), cvt2h(v.z, v.w));
    }
}

// ============================================================================
// GEMM v3 (fp16x2): C[M,N] = A[M,K]*W[N,K]^T + bias. A fp16, W hi/lo fp16.
// 128x128 CTA tile, 512 threads, K-chunk 32, 4-stage cp.async, ldmatrix+swizzle.
// MODE 0: scatter q (fp16, scaled) / k,v (fp16 hi/lo). MODE 1: fp32 + bias.
// ============================================================================
#define GBK 32
#define GNC (EE / GBK)          // 32 chunks
#define GS_A  0
#define GS_BH 8192
#define GS_BL 16384
#define G_STAGE 24576
#define GEMM_SMEM3 (4 * G_STAGE)   // 98304

template <int MODE>
__global__ __launch_bounds__(512, 1)
void mma_gemm3(const __half* __restrict__ Ag,
               const __half* __restrict__ Bgh, const __half* __restrict__ Bgl,
               const float* __restrict__ bias, float* __restrict__ Cout)
{
    extern __shared__ char smem[];
    const uint32_t sb = smem_u32(smem);

    const int tid  = threadIdx.x;
    const int wid  = tid >> 5;
    const int lane = tid & 31;
    const int g    = lane >> 2;
    const int t    = lane & 3;
    const int wm   = (wid >> 2) << 5;   // 0..96
    const int wn   = (wid & 3) << 5;    // 0..96
    const int row0 = blockIdx.y * 128;
    const int col0 = blockIdx.x * 128;
    const int rK   = (lane & 7) + ((lane >> 4) & 1) * 8;
    const int cKb  = (lane >> 3) & 1;

    float acc[2][4][4];
#pragma unroll
    for (int i = 0; i < 2; i++)
#pragma unroll
        for (int j = 0; j < 4; j++)
#pragma unroll
            for (int k = 0; k < 4; k++) acc[i][j][k] = 0.0f;

    // copy lane map: 128 rows x 4 x 16B groups per matrix; 1 group/thread
    const int cr = tid >> 2;
    const int cg = tid & 3;
    const uint32_t s_off = (uint32_t)cr * 64 + (uint32_t)((cg ^ ((cr >> 1) & 3)) << 4);
    const size_t gA0 = (size_t)(row0 + cr) * EE + cg * 8;
    const size_t gB0 = (size_t)(col0 + cr) * EE + cg * 8;

    auto issue = [&](int c) {
        uint32_t st = sb + (uint32_t)(c & 3) * G_STAGE;
        size_t ka = gA0 + (size_t)c * GBK;
        size_t kb = gB0 + (size_t)c * GBK;
        CP16(st + GS_A + s_off, Ag + ka);
        CP16(st + GS_BH + s_off, Bgh + kb);
        CP16(st + GS_BL + s_off, Bgl + kb);
        CP_COMMIT();
    };

    auto compute = [&](int stage) {
        uint32_t base = sb + (uint32_t)stage * G_STAGE;
#pragma unroll
        for (int ks = 0; ks < 2; ks++) {
            uint32_t ah[2][4];
#pragma unroll
            for (int ma = 0; ma < 2; ma++) {
                int row  = wm + 16 * ma + (lane & 15);
                int cgrp = ks * 2 + (lane >> 4);
                uint32_t ad = base + GS_A + row * 64 + ((cgrp ^ ((row >> 1) & 3)) << 4);
                LDSM_X4(ah[ma][0], ah[ma][1], ah[ma][2], ah[ma][3], ad);
            }
            uint32_t bh2[4][2], bl2[4][2];
#pragma unroll
            for (int jj = 0; jj < 2; jj++) {
                int row  = wn + 16 * jj + rK;
                int cgrp = ks * 2 + cKb;
                uint32_t ad = base + GS_BH + row * 64 + ((cgrp ^ ((row >> 1) & 3)) << 4);
                LDSM_X4(bh2[2 * jj][0], bh2[2 * jj][1], bh2[2 * jj + 1][0], bh2[2 * jj + 1][1], ad);
                LDSM_X4(bl2[2 * jj][0], bl2[2 * jj][1], bl2[2 * jj + 1][0], bl2[2 * jj + 1][1], ad + 8192);
            }
#pragma unroll
            for (int ma = 0; ma < 2; ma++)
#pragma unroll
                for (int na = 0; na < 4; na++) mma_f16(acc[ma][na], ah[ma], bh2[na]);
#pragma unroll
            for (int ma = 0; ma < 2; ma++)
#pragma unroll
                for (int na = 0; na < 4; na++) mma_f16(acc[ma][na], ah[ma], bl2[na]);
        }
    };

    issue(0);
    issue(1);
    issue(2);
    for (int c = 0; c < GNC; c++) {
        if (c + 3 < GNC) { CP_WAIT(2); } else { CP_WAIT(0); }
        __syncthreads();
        if (c + 3 < GNC) issue(c + 3);
        compute(c & 3);
    }

    // ---- epilogue ----
#pragma unroll
    for (int na = 0; na < 4; na++) {
        const int f0 = col0 + wn + 8 * na + 2 * t;
        const float b0 = bias[f0];
        const float b1 = bias[f0 + 1];
        if (MODE == 0) {
            int h     = f0 / 192;
            int rem   = f0 - 192 * h;
            int which = rem >> 6;
            int dd    = rem & 63;
#pragma unroll
            for (int ma = 0; ma < 2; ma++) {
                const float* d4 = acc[ma][na];
                int tb = row0 + wm + 16 * ma + g;
#pragma unroll
                for (int hh = 0; hh < 2; hh++) {
                    int tbx = tb + 8 * hh;
                    int tt = tbx >> 1, bb = tbx & 1;
                    size_t off = ((size_t)(bb * HH + h) * TQ + tt) * DD + dd;
                    float x = d4[2 * hh] + b0, y = d4[2 * hh + 1] + b1;
                    if (which == 0) {
                        *(uint32_t*)(g_q16 + off) = cvt2h(x * QSCALE, y * QSCALE);
                    } else {
                        __half* dh = (which == 1) ? g_kh : g_vh;
                        __half* dl = (which == 1) ? g_kl : g_vl;
                        uint32_t hi, lo;
                        split2h(x, y, hi, lo);
                        *(uint32_t*)(dh + off) = hi;
                        *(uint32_t*)(dl + off) = lo;
                    }
                }
            }
        } else {
#pragma unroll
            for (int ma = 0; ma < 2; ma++) {
                const float* d4 = acc[ma][na];
                int r = row0 + wm + 16 * ma + g;
                *(float2*)(Cout + (size_t)r * EE + f0) = make_float2(d4[0] + b0, d4[1] + b1);
                *(float2*)(Cout + (size_t)(r + 8) * EE + f0) = make_float2(d4[2] + b0, d4[3] + b1);
            }
        }
    }
}

// ============================================================================
// Flash attention v3 (fp16x2): Q fp16 single, K/V hi/lo fp16, cp.async DB.
// CTA: 128 q-rows of one (b,h), 8 warps x 16 rows, KV tiles of 64.
// ============================================================================
#define AQ3   0                    // Q: 16KB
#define AKV3  16384                // per stage: KH 0, KL 8192, VH 16384, VL 24576
#define AKV_ST3 32768
#define ATTN_SMEM3 (AKV3 + 2 * AKV_ST3)    // 81920

__global__ __launch_bounds__(256, 1)
void attn_mma3()
{
    extern __shared__ char sm[];
    const uint32_t sb = smem_u32(sm);

    const int tid  = threadIdx.x;
    const int wid  = tid >> 5;
    const int lane = tid & 31;
    const int g    = lane >> 2;
    const int t    = lane & 3;

    const int bh = blockIdx.y;
    const int b  = bh >> 4;
    const int h  = bh & 15;
    const size_t base = (size_t)bh * TQ * DD;
    const int t0 = blockIdx.x * 128;
    const int m0 = wid * 16;

    const int rK  = (lane & 7) + ((lane >> 4) & 1) * 8;
    const int cKb = (lane >> 3) & 1;
    const int rV  = (lane & 7) + ((lane >> 3) & 1) * 8;
    const int cVb = (lane >> 4) & 1;

    // copy lane map: rows of 128B, 8 x 16B groups, swizzle c ^ (r&7)
    auto issueQ = [&]() {
#pragma unroll
        for (int p = 0; p < 4; p++) {
            int id = tid + p * 256;
            int r = id >> 3, cgp = id & 7;
            uint32_t so = (uint32_t)r * 128 + ((cgp ^ (r & 7)) << 4);
            CP16(sb + AQ3 + so, g_q16 + base + (size_t)(t0 + r) * DD + cgp * 8);
        }
        CP_COMMIT();
    };
    auto issueKV = [&](int st, int buf) {
        uint32_t kvb = sb + AKV3 + (uint32_t)buf * AKV_ST3;
#pragma unroll
        for (int p = 0; p < 2; p++) {
            int id = tid + p * 256;
            int r = id >> 3, cgp = id & 7;
            uint32_t so = (uint32_t)r * 128 + ((cgp ^ (r & 7)) << 4);
            size_t go = base + (size_t)(st + r) * DD + cgp * 8;
            CP16(kvb + so,         g_kh + go);
            CP16(kvb + 8192 + so,  g_kl + go);
            CP16(kvb + 16384 + so, g_vh + go);
            CP16(kvb + 24576 + so, g_vl + go);
        }
        CP_COMMIT();
    };

    issueQ();
    issueKV(0, 0);
    CP_WAIT(0);
    __syncthreads();

    // ---- Q fragments (persistent, fp16 single) ----
    uint32_t qh[4][4];
    {
        int row = m0 + (lane & 15);
#pragma unroll
        for (int ks = 0; ks < 4; ks++) {
            int cgrp = ks * 2 + (lane >> 4);
            uint32_t a = sb + AQ3 + row * 128 + ((cgrp ^ (row & 7)) << 4);
            LDSM_X4(qh[ks][0], qh[ks][1], qh[ks][2], qh[ks][3], a);
        }
    }

    float O[8][4];
#pragma unroll
    for (int j = 0; j < 8; j++)
#pragma unroll
        for (int k = 0; k < 4; k++) O[j][k] = 0.0f;
    float mrow0 = -1e30f, mrow1 = -1e30f, lrow0 = 0.0f, lrow1 = 0.0f;

    for (int i = 0; i < TQ / 64; i++) {
        if (i > 0) {
            CP_WAIT(0);
            __syncthreads();
        }
        if (i + 1 < TQ / 64) issueKV((i + 1) * 64, (i + 1) & 1);

        uint32_t kvb = sb + AKV3 + (uint32_t)(i & 1) * AKV_ST3;

        // ---- S = Q K^T (2-pass) ----
        float S[8][4];
#pragma unroll
        for (int j = 0; j < 8; j++)
#pragma unroll
            for (int k = 0; k < 4; k++) S[j][k] = 0.0f;

#pragma unroll
        for (int ks = 0; ks < 4; ks++) {
            uint32_t bh_[8][2], bl_[8][2];
#pragma unroll
            for (int jj = 0; jj < 4; jj++) {
                int row  = 16 * jj + rK;
                int cgrp = ks * 2 + cKb;
                uint32_t a = kvb + row * 128 + ((cgrp ^ (row & 7)) << 4);
                LDSM_X4(bh_[2 * jj][0], bh_[2 * jj][1], bh_[2 * jj + 1][0], bh_[2 * jj + 1][1], a);
                LDSM_X4(bl_[2 * jj][0], bl_[2 * jj][1], bl_[2 * jj + 1][0], bl_[2 * jj + 1][1], a + 8192);
            }
#pragma unroll
            for (int j = 0; j < 8; j++) mma_f16(S[j], qh[ks], bh_[j]);
#pragma unroll
            for (int j = 0; j < 8; j++) mma_f16(S[j], qh[ks], bl_[j]);
        }

        // ---- online softmax (base-2) ----
        float mx0 = -1e30f, mx1 = -1e30f;
#pragma unroll
        for (int j = 0; j < 8; j++) {
            mx0 = fmaxf(mx0, fmaxf(S[j][0], S[j][1]));
            mx1 = fmaxf(mx1, fmaxf(S[j][2], S[j][3]));
        }
        mx0 = fmaxf(mx0, __shfl_xor_sync(0xffffffffu, mx0, 1));
        mx0 = fmaxf(mx0, __shfl_xor_sync(0xffffffffu, mx0, 2));
        mx1 = fmaxf(mx1, __shfl_xor_sync(0xffffffffu, mx1, 1));
        mx1 = fmaxf(mx1, __shfl_xor_sync(0xffffffffu, mx1, 2));
        float mn0 = fmaxf(mrow0, mx0), mn1 = fmaxf(mrow1, mx1);
        float sc0 = ex2f(mrow0 - mn0), sc1 = ex2f(mrow1 - mn1);
        float s0 = 0.0f, s1 = 0.0f;
#pragma unroll
        for (int j = 0; j < 8; j++) {
            S[j][0] = ex2f(S[j][0] - mn0);
            S[j][1] = ex2f(S[j][1] - mn0);
            S[j][2] = ex2f(S[j][2] - mn1);
            S[j][3] = ex2f(S[j][3] - mn1);
            s0 += S[j][0] + S[j][1];
            s1 += S[j][2] + S[j][3];
        }
        s0 += __shfl_xor_sync(0xffffffffu, s0, 1);
        s0 += __shfl_xor_sync(0xffffffffu, s0, 2);
        s1 += __shfl_xor_sync(0xffffffffu, s1, 1);
        s1 += __shfl_xor_sync(0xffffffffu, s1, 2);
        lrow0 = lrow0 * sc0 + s0;
        lrow1 = lrow1 * sc1 + s1;
        mrow0 = mn0;
        mrow1 = mn1;
#pragma unroll
        for (int j = 0; j < 8; j++) {
            O[j][0] *= sc0; O[j][1] *= sc0;
            O[j][2] *= sc1; O[j][3] *= sc1;
        }

        // ---- P fragments (fp16 single, straight from S accumulators) ----
        uint32_t ph[4][4];
#pragma unroll
        for (int kk = 0; kk < 4; kk++) {
            ph[kk][0] = cvt2h(S[2 * kk][0],     S[2 * kk][1]);
            ph[kk][1] = cvt2h(S[2 * kk][2],     S[2 * kk][3]);
            ph[kk][2] = cvt2h(S[2 * kk + 1][0], S[2 * kk + 1][1]);
            ph[kk][3] = cvt2h(S[2 * kk + 1][2], S[2 * kk + 1][3]);
        }

        // ---- O += P V (2-pass) ----
#pragma unroll
        for (int kk = 0; kk < 4; kk++) {
            uint32_t vh_[8][2], vl_[8][2];
#pragma unroll
            for (int jj = 0; jj < 4; jj++) {
                int row  = kk * 16 + rV;
                int cgrp = jj * 2 + cVb;
                uint32_t a = kvb + 16384 + row * 128 + ((cgrp ^ (row & 7)) << 4);
                LDSM_X4_T(vh_[2 * jj][0], vh_[2 * jj][1], vh_[2 * jj + 1][0], vh_[2 * jj + 1][1], a);
                LDSM_X4_T(vl_[2 * jj][0], vl_[2 * jj][1], vl_[2 * jj + 1][0], vl_[2 * jj + 1][1], a + 8192);
            }
#pragma unroll
            for (int j = 0; j < 8; j++) mma_f16(O[j], ph[kk], vh_[j]);
#pragma unroll
            for (int j = 0; j < 8; j++) mma_f16(O[j], ph[kk], vl_[j]);
        }
    }

    // ---- epilogue: ctx fp16 single, layout [TB, EE] ----
    float inv0 = 1.0f / lrow0, inv1 = 1.0f / lrow1;
    int qr0 = t0 + m0 + g;
    int qr1 = qr0 + 8;
#pragma unroll
    for (int j = 0; j < 8; j++) {
        int col = h * 64 + 8 * j + 2 * t;
        *(uint32_t*)(g_ctx16 + (size_t)(qr0 * BB + b) * EE + col) =
            cvt2h(O[j][0] * inv0, O[j][1] * inv0);
        *(uint32_t*)(g_ctx16 + (size_t)(qr1 * BB + b) * EE + col) =
            cvt2h(O[j][2] * inv1, O[j][3] * inv1);
    }
}

// ============================================================================
// Launch
// ============================================================================
extern "C" void kernel_launch(void* const* d_in, const int* in_sizes, int n_in,
                              void* d_out, int out_size)
{
    const float* query = (const float*)d_in[0];
    const float* w_in  = (const float*)d_in[1];
    const float* b_in  = (const float*)d_in[2];
    const float* w_out = (const float*)d_in[3];
    const float* b_out = (const float*)d_in[4];
    float* out = (float*)d_out;

    __half *p_qry16, *p_wih, *p_wil, *p_woh, *p_wol, *p_ctx16;
    cudaGetSymbolAddress((void**)&p_qry16, g_qry16);
    cudaGetSymbolAddress((void**)&p_wih, g_wih);
    cudaGetSymbolAddress((void**)&p_wil, g_wil);
    cudaGetSymbolAddress((void**)&p_woh, g_woh);
    cudaGetSymbolAddress((void**)&p_wol, g_wol);
    cudaGetSymbolAddress((void**)&p_ctx16, g_ctx16);

    cudaFuncSetAttribute(mma_gemm3<0>, cudaFuncAttributeMaxDynamicSharedMemorySize, GEMM_SMEM3);
    cudaFuncSetAttribute(mma_gemm3<1>, cudaFuncAttributeMaxDynamicSharedMemorySize, GEMM_SMEM3);
    cudaFuncSetAttribute(attn_mma3, cudaFuncAttributeMaxDynamicSharedMemorySize, ATTN_SMEM3);

    // 0) converts: query -> fp16; weights -> fp16 hi/lo
    cvt16_kernel<<<(TB * EE / 4 + 255) / 256, 256>>>(query, p_qry16, TB * EE / 4);
    split16_kernel<<<(FF * EE / 4 + 255) / 256, 256>>>(w_in, p_wih, p_wil, FF * EE / 4);
    split16_kernel<<<(EE * EE / 4 + 255) / 256, 256>>>(w_out, p_woh, p_wol, EE * EE / 4);

    // 1) QKV projection (fp16x2) -> q fp16 (scaled) / k,v hi/lo
    mma_gemm3<0><<<dim3(FF / 128, TB / 128), 512, GEMM_SMEM3>>>(p_qry16, p_wih, p_wil, b_in, nullptr);
    // 2) Flash attention (fp16x2) -> ctx fp16
    attn_mma3<<<dim3(TQ / 128, BB * HH), 256, ATTN_SMEM3>>>();
    // 3) Output projection (fp16x2) -> fp32 out
    mma_gemm3<1><<<dim3(EE / 128, TB / 128), 512, GEMM_SMEM3>>>(p_ctx16, p_woh, p_wol, b_out, out);
}

// round 8
// speedup vs baseline: 4.6787x; 1.1798x over previous
#include <cuda_runtime.h>
#include <cuda_fp16.h>
#include <math.h>
#include <cstdint>

// Problem constants
#define TQ 2048
#define BB 2
#define EE 1024
#define HH 16
#define DD 64
#define TB 4096          // TQ*BB
#define FF 3072          // 3*EE

#define QSCALE (0.125f * 1.44269504088896f)   // d^-0.5 * log2(e)  (softmax uses ex2)

// Scratch (allocation-free rule: __device__ globals)
__device__ __half g_qry16[(size_t)TB * EE];                       // A for gemm0 (fp16)
__device__ __half g_wih[(size_t)FF * EE], g_wil[(size_t)FF * EE]; // W_in hi/lo
__device__ __half g_woh[(size_t)EE * EE], g_wol[(size_t)EE * EE]; // W_out hi/lo
__device__ __half g_q16[(size_t)BB * HH * TQ * DD];               // Q fp16 (pre-scaled)
__device__ __half g_kh[(size_t)BB * HH * TQ * DD], g_kl[(size_t)BB * HH * TQ * DD];
__device__ __half g_vh[(size_t)BB * HH * TQ * DD], g_vl[(size_t)BB * HH * TQ * DD];
__device__ __half g_ctx16[(size_t)TB * EE];                       // A for gemm1 (fp16)

// ============================================================================
// helpers
// ============================================================================
__device__ __forceinline__ uint32_t smem_u32(const void* p) {
    uint32_t a;
    asm("{ .reg .u64 t; cvta.to.shared.u64 t, %1; cvt.u32.u64 %0, t; }" : "=r"(a) : "l"(p));
    return a;
}
__device__ __forceinline__ uint32_t cvt2h(float x, float y) {
    __half2 h = __floats2half2_rn(x, y);
    return *(uint32_t*)&h;
}
// split (x,y) into packed fp16 hi and lo words (x in low half)
__device__ __forceinline__ void split2h(float x, float y, uint32_t& hi, uint32_t& lo) {
    __half hx = __float2half_rn(x), hy = __float2half_rn(y);
    float rx = x - __half2float(hx), ry = y - __half2float(hy);
    __half2 h = __halves2half2(hx, hy);
    hi = *(uint32_t*)&h;
    lo = cvt2h(rx, ry);
}
__device__ __forceinline__ float ex2f(float x) {
    float y;
    asm("ex2.approx.f32 %0, %1;" : "=f"(y) : "f"(x));
    return y;
}
__device__ __forceinline__ void mma_f16(float* d, const uint32_t* a, const uint32_t* b) {
    asm volatile(
        "mma.sync.aligned.m16n8k16.row.col.f32.f16.f16.f32 "
        "{%0,%1,%2,%3}, {%4,%5,%6,%7}, {%8,%9}, {%0,%1,%2,%3};"
        : "+f"(d[0]), "+f"(d[1]), "+f"(d[2]), "+f"(d[3])
        : "r"(a[0]), "r"(a[1]), "r"(a[2]), "r"(a[3]), "r"(b[0]), "r"(b[1]));
}
#define LDSM_X4(R0,R1,R2,R3,ADDR) \
    asm volatile("ldmatrix.sync.aligned.m8n8.x4.shared.b16 {%0,%1,%2,%3}, [%4];" \
        : "=r"(R0), "=r"(R1), "=r"(R2), "=r"(R3) : "r"(ADDR))
#define LDSM_X4_T(R0,R1,R2,R3,ADDR) \
    asm volatile("ldmatrix.sync.aligned.m8n8.x4.trans.shared.b16 {%0,%1,%2,%3}, [%4];" \
        : "=r"(R0), "=r"(R1), "=r"(R2), "=r"(R3) : "r"(ADDR))
#define CP16(SM, GP) \
    asm volatile("cp.async.cg.shared.global [%0], [%1], 16;" :: "r"(SM), "l"(GP) : "memory")
#define CP_COMMIT() asm volatile("cp.async.commit_group;" ::: "memory")
#define CP_WAIT(N)  asm volatile("cp.async.wait_group %0;" :: "n"(N) : "memory")

// ============================================================================
// elementwise converters (HBM-bound, one-time)
// ============================================================================
__global__ void split16_kernel(const float* __restrict__ src,
                               __half* __restrict__ hi, __half* __restrict__ lo, int n4)
{
    int i = blockIdx.x * blockDim.x + threadIdx.x;
    if (i < n4) {
        float4 v = ((const float4*)src)[i];
        uint32_t h0, l0, h1, l1;
        split2h(v.x, v.y, h0, l0);
        split2h(v.z, v.w, h1, l1);
        ((uint2*)hi)[i] = make_uint2(h0, h1);
        ((uint2*)lo)[i] = make_uint2(l0, l1);
    }
}
__global__ void cvt16_kernel(const float* __restrict__ src, __half* __restrict__ dst, int n4)
{
    int i = blockIdx.x * blockDim.x + threadIdx.x;
    if (i < n4) {
        float4 v = ((const float4*)src)[i];
        ((uint2*)dst)[i] = make_uint2(cvt2h(v.x, v.y), cvt2h(v.z, v.w));
    }
}

// ============================================================================
// GEMM v4 (fp16x2): 256 threads, 128x128 CTA tile, warp tile 64x32,
// 4-stage cp.async, 2 CTAs/SM. A fp16 single, W hi/lo.
// MODE 0: scatter q (fp16, scaled) / k,v (fp16 hi/lo). MODE 1: fp32 + bias.
// ============================================================================
#define GBK 32
#define GNC (EE / GBK)          // 32 chunks
#define GS_A  0
#define GS_BH 8192
#define GS_BL 16384
#define G_STAGE 24576
#define GEMM_SMEM4 (4 * G_STAGE)   // 98304

template <int MODE>
__global__ __launch_bounds__(256, 2)
void mma_gemm4(const __half* __restrict__ Ag,
               const __half* __restrict__ Bgh, const __half* __restrict__ Bgl,
               const float* __restrict__ bias, float* __restrict__ Cout)
{
    extern __shared__ char smem[];
    const uint32_t sb = smem_u32(smem);

    const int tid  = threadIdx.x;
    const int wid  = tid >> 5;
    const int lane = tid & 31;
    const int g    = lane >> 2;
    const int t    = lane & 3;
    const int wm   = (wid >> 2) << 6;   // 0 or 64
    const int wn   = (wid & 3) << 5;    // 0..96
    const int row0 = blockIdx.y * 128;
    const int col0 = blockIdx.x * 128;
    const int rK   = (lane & 7) + ((lane >> 4) & 1) * 8;
    const int cKb  = (lane >> 3) & 1;

    float acc[4][4][4];
#pragma unroll
    for (int i = 0; i < 4; i++)
#pragma unroll
        for (int j = 0; j < 4; j++)
#pragma unroll
            for (int k = 0; k < 4; k++) acc[i][j][k] = 0.0f;

    auto issue = [&](int c) {
        uint32_t st = sb + (uint32_t)(c & 3) * G_STAGE;
#pragma unroll
        for (int p = 0; p < 2; p++) {
            int id = tid + p * 256;
            int r  = id >> 2;
            int cg = id & 3;
            uint32_t so = (uint32_t)r * 64 + (uint32_t)((cg ^ ((r >> 1) & 3)) << 4);
            size_t ka = (size_t)(row0 + r) * EE + cg * 8 + (size_t)c * GBK;
            size_t kb = (size_t)(col0 + r) * EE + cg * 8 + (size_t)c * GBK;
            CP16(st + GS_A + so, Ag + ka);
            CP16(st + GS_BH + so, Bgh + kb);
            CP16(st + GS_BL + so, Bgl + kb);
        }
        CP_COMMIT();
    };

    auto compute = [&](int stage) {
        uint32_t base = sb + (uint32_t)stage * G_STAGE;
#pragma unroll
        for (int ks = 0; ks < 2; ks++) {
            uint32_t ah[4][4];
#pragma unroll
            for (int ma = 0; ma < 4; ma++) {
                int row  = wm + 16 * ma + (lane & 15);
                int cgrp = ks * 2 + (lane >> 4);
                uint32_t ad = base + GS_A + row * 64 + ((cgrp ^ ((row >> 1) & 3)) << 4);
                LDSM_X4(ah[ma][0], ah[ma][1], ah[ma][2], ah[ma][3], ad);
            }
            uint32_t bh2[4][2], bl2[4][2];
#pragma unroll
            for (int jj = 0; jj < 2; jj++) {
                int row  = wn + 16 * jj + rK;
                int cgrp = ks * 2 + cKb;
                uint32_t ad = base + GS_BH + row * 64 + ((cgrp ^ ((row >> 1) & 3)) << 4);
                LDSM_X4(bh2[2 * jj][0], bh2[2 * jj][1], bh2[2 * jj + 1][0], bh2[2 * jj + 1][1], ad);
                LDSM_X4(bl2[2 * jj][0], bl2[2 * jj][1], bl2[2 * jj + 1][0], bl2[2 * jj + 1][1], ad + 8192);
            }
#pragma unroll
            for (int ma = 0; ma < 4; ma++)
#pragma unroll
                for (int na = 0; na < 4; na++) mma_f16(acc[ma][na], ah[ma], bh2[na]);
#pragma unroll
            for (int ma = 0; ma < 4; ma++)
#pragma unroll
                for (int na = 0; na < 4; na++) mma_f16(acc[ma][na], ah[ma], bl2[na]);
        }
    };

    issue(0);
    issue(1);
    issue(2);
    for (int c = 0; c < GNC; c++) {
        if (c + 3 < GNC) { CP_WAIT(2); } else { CP_WAIT(0); }
        __syncthreads();
        if (c + 3 < GNC) issue(c + 3);
        compute(c & 3);
    }

    // ---- epilogue ----
#pragma unroll
    for (int na = 0; na < 4; na++) {
        const int f0 = col0 + wn + 8 * na + 2 * t;
        const float b0 = bias[f0];
        const float b1 = bias[f0 + 1];
        if (MODE == 0) {
            int h     = f0 / 192;
            int rem   = f0 - 192 * h;
            int which = rem >> 6;
            int dd    = rem & 63;
#pragma unroll
            for (int ma = 0; ma < 4; ma++) {
                const float* d4 = acc[ma][na];
                int tb = row0 + wm + 16 * ma + g;
#pragma unroll
                for (int hh = 0; hh < 2; hh++) {
                    int tbx = tb + 8 * hh;
                    int tt = tbx >> 1, bb = tbx & 1;
                    size_t off = ((size_t)(bb * HH + h) * TQ + tt) * DD + dd;
                    float x = d4[2 * hh] + b0, y = d4[2 * hh + 1] + b1;
                    if (which == 0) {
                        *(uint32_t*)(g_q16 + off) = cvt2h(x * QSCALE, y * QSCALE);
                    } else {
                        __half* dh = (which == 1) ? g_kh : g_vh;
                        __half* dl = (which == 1) ? g_kl : g_vl;
                        uint32_t hi, lo;
                        split2h(x, y, hi, lo);
                        *(uint32_t*)(dh + off) = hi;
                        *(uint32_t*)(dl + off) = lo;
                    }
                }
            }
        } else {
#pragma unroll
            for (int ma = 0; ma < 4; ma++) {
                const float* d4 = acc[ma][na];
                int r = row0 + wm + 16 * ma + g;
                *(float2*)(Cout + (size_t)r * EE + f0) = make_float2(d4[0] + b0, d4[1] + b1);
                *(float2*)(Cout + (size_t)(r + 8) * EE + f0) = make_float2(d4[2] + b0, d4[3] + b1);
            }
        }
    }
}

// ============================================================================
// Flash attention v3 (fp16x2): Q fp16 single, K/V hi/lo fp16, cp.async DB.
// CTA: 128 q-rows of one (b,h), 8 warps x 16 rows, KV tiles of 64. 2 CTAs/SM.
// ============================================================================
#define AQ3   0                    // Q: 16KB
#define AKV3  16384                // per stage: KH 0, KL 8192, VH 16384, VL 24576
#define AKV_ST3 32768
#define ATTN_SMEM3 (AKV3 + 2 * AKV_ST3)    // 81920

__global__ __launch_bounds__(256, 2)
void attn_mma3()
{
    extern __shared__ char sm[];
    const uint32_t sb = smem_u32(sm);

    const int tid  = threadIdx.x;
    const int wid  = tid >> 5;
    const int lane = tid & 31;
    const int g    = lane >> 2;
    const int t    = lane & 3;

    const int bh = blockIdx.y;
    const int b  = bh >> 4;
    const int h  = bh & 15;
    const size_t base = (size_t)bh * TQ * DD;
    const int t0 = blockIdx.x * 128;
    const int m0 = wid * 16;

    const int rK  = (lane & 7) + ((lane >> 4) & 1) * 8;
    const int cKb = (lane >> 3) & 1;
    const int rV  = (lane & 7) + ((lane >> 3) & 1) * 8;
    const int cVb = (lane >> 4) & 1;

    auto issueQ = [&]() {
#pragma unroll
        for (int p = 0; p < 4; p++) {
            int id = tid + p * 256;
            int r = id >> 3, cgp = id & 7;
            uint32_t so = (uint32_t)r * 128 + ((cgp ^ (r & 7)) << 4);
            CP16(sb + AQ3 + so, g_q16 + base + (size_t)(t0 + r) * DD + cgp * 8);
        }
        CP_COMMIT();
    };
    auto issueKV = [&](int st, int buf) {
        uint32_t kvb = sb + AKV3 + (uint32_t)buf * AKV_ST3;
#pragma unroll
        for (int p = 0; p < 2; p++) {
            int id = tid + p * 256;
            int r = id >> 3, cgp = id & 7;
            uint32_t so = (uint32_t)r * 128 + ((cgp ^ (r & 7)) << 4);
            size_t go = base + (size_t)(st + r) * DD + cgp * 8;
            CP16(kvb + so,         g_kh + go);
            CP16(kvb + 8192 + so,  g_kl + go);
            CP16(kvb + 16384 + so, g_vh + go);
            CP16(kvb + 24576 + so, g_vl + go);
        }
        CP_COMMIT();
    };

    issueQ();
    issueKV(0, 0);
    CP_WAIT(0);
    __syncthreads();

    // ---- Q fragments (persistent, fp16 single) ----
    uint32_t qh[4][4];
    {
        int row = m0 + (lane & 15);
#pragma unroll
        for (int ks = 0; ks < 4; ks++) {
            int cgrp = ks * 2 + (lane >> 4);
            uint32_t a = sb + AQ3 + row * 128 + ((cgrp ^ (row & 7)) << 4);
            LDSM_X4(qh[ks][0], qh[ks][1], qh[ks][2], qh[ks][3], a);
        }
    }

    float O[8][4];
#pragma unroll
    for (int j = 0; j < 8; j++)
#pragma unroll
        for (int k = 0; k < 4; k++) O[j][k] = 0.0f;
    float mrow0 = -1e30f, mrow1 = -1e30f, lrow0 = 0.0f, lrow1 = 0.0f;

    for (int i = 0; i < TQ / 64; i++) {
        if (i > 0) {
            CP_WAIT(0);
            __syncthreads();
        }
        if (i + 1 < TQ / 64) issueKV((i + 1) * 64, (i + 1) & 1);

        uint32_t kvb = sb + AKV3 + (uint32_t)(i & 1) * AKV_ST3;

        // ---- S = Q K^T (2-pass) ----
        float S[8][4];
#pragma unroll
        for (int j = 0; j < 8; j++)
#pragma unroll
            for (int k = 0; k < 4; k++) S[j][k] = 0.0f;

#pragma unroll
        for (int ks = 0; ks < 4; ks++) {
            uint32_t bh_[8][2], bl_[8][2];
#pragma unroll
            for (int jj = 0; jj < 4; jj++) {
                int row  = 16 * jj + rK;
                int cgrp = ks * 2 + cKb;
                uint32_t a = kvb + row * 128 + ((cgrp ^ (row & 7)) << 4);
                LDSM_X4(bh_[2 * jj][0], bh_[2 * jj][1], bh_[2 * jj + 1][0], bh_[2 * jj + 1][1], a);
                LDSM_X4(bl_[2 * jj][0], bl_[2 * jj][1], bl_[2 * jj + 1][0], bl_[2 * jj + 1][1], a + 8192);
            }
#pragma unroll
            for (int j = 0; j < 8; j++) mma_f16(S[j], qh[ks], bh_[j]);
#pragma unroll
            for (int j = 0; j < 8; j++) mma_f16(S[j], qh[ks], bl_[j]);
        }

        // ---- online softmax (base-2) ----
        float mx0 = -1e30f, mx1 = -1e30f;
#pragma unroll
        for (int j = 0; j < 8; j++) {
            mx0 = fmaxf(mx0, fmaxf(S[j][0], S[j][1]));
            mx1 = fmaxf(mx1, fmaxf(S[j][2], S[j][3]));
        }
        mx0 = fmaxf(mx0, __shfl_xor_sync(0xffffffffu, mx0, 1));
        mx0 = fmaxf(mx0, __shfl_xor_sync(0xffffffffu, mx0, 2));
        mx1 = fmaxf(mx1, __shfl_xor_sync(0xffffffffu, mx1, 1));
        mx1 = fmaxf(mx1, __shfl_xor_sync(0xffffffffu, mx1, 2));
        float mn0 = fmaxf(mrow0, mx0), mn1 = fmaxf(mrow1, mx1);
        float sc0 = ex2f(mrow0 - mn0), sc1 = ex2f(mrow1 - mn1);
        float s0 = 0.0f, s1 = 0.0f;
#pragma unroll
        for (int j = 0; j < 8; j++) {
            S[j][0] = ex2f(S[j][0] - mn0);
            S[j][1] = ex2f(S[j][1] - mn0);
            S[j][2] = ex2f(S[j][2] - mn1);
            S[j][3] = ex2f(S[j][3] - mn1);
            s0 += S[j][0] + S[j][1];
            s1 += S[j][2] + S[j][3];
        }
        s0 += __shfl_xor_sync(0xffffffffu, s0, 1);
        s0 += __shfl_xor_sync(0xffffffffu, s0, 2);
        s1 += __shfl_xor_sync(0xffffffffu, s1, 1);
        s1 += __shfl_xor_sync(0xffffffffu, s1, 2);
        lrow0 = lrow0 * sc0 + s0;
        lrow1 = lrow1 * sc1 + s1;
        mrow0 = mn0;
        mrow1 = mn1;
#pragma unroll
        for (int j = 0; j < 8; j++) {
            O[j][0] *= sc0; O[j][1] *= sc0;
            O[j][2] *= sc1; O[j][3] *= sc1;
        }

        // ---- P fragments (fp16 single, straight from S accumulators) ----
        uint32_t ph[4][4];
#pragma unroll
        for (int kk = 0; kk < 4; kk++) {
            ph[kk][0] = cvt2h(S[2 * kk][0],     S[2 * kk][1]);
            ph[kk][1] = cvt2h(S[2 * kk][2],     S[2 * kk][3]);
            ph[kk][2] = cvt2h(S[2 * kk + 1][0], S[2 * kk + 1][1]);
            ph[kk][3] = cvt2h(S[2 * kk + 1][2], S[2 * kk + 1][3]);
        }

        // ---- O += P V (2-pass) ----
#pragma unroll
        for (int kk = 0; kk < 4; kk++) {
            uint32_t vh_[8][2], vl_[8][2];
#pragma unroll
            for (int jj = 0; jj < 4; jj++) {
                int row  = kk * 16 + rV;
                int cgrp = jj * 2 + cVb;
                uint32_t a = kvb + 16384 + row * 128 + ((cgrp ^ (row & 7)) << 4);
                LDSM_X4_T(vh_[2 * jj][0], vh_[2 * jj][1], vh_[2 * jj + 1][0], vh_[2 * jj + 1][1], a);
                LDSM_X4_T(vl_[2 * jj][0], vl_[2 * jj][1], vl_[2 * jj + 1][0], vl_[2 * jj + 1][1], a + 8192);
            }
#pragma unroll
            for (int j = 0; j < 8; j++) mma_f16(O[j], ph[kk], vh_[j]);
#pragma unroll
            for (int j = 0; j < 8; j++) mma_f16(O[j], ph[kk], vl_[j]);
        }
    }

    // ---- epilogue: ctx fp16 single, layout [TB, EE] ----
    float inv0 = 1.0f / lrow0, inv1 = 1.0f / lrow1;
    int qr0 = t0 + m0 + g;
    int qr1 = qr0 + 8;
#pragma unroll
    for (int j = 0; j < 8; j++) {
        int col = h * 64 + 8 * j + 2 * t;
        *(uint32_t*)(g_ctx16 + (size_t)(qr0 * BB + b) * EE + col) =
            cvt2h(O[j][0] * inv0, O[j][1] * inv0);
        *(uint32_t*)(g_ctx16 + (size_t)(qr1 * BB + b) * EE + col) =
            cvt2h(O[j][2] * inv1, O[j][3] * inv1);
    }
}

// ============================================================================
// Launch
// ============================================================================
extern "C" void kernel_launch(void* const* d_in, const int* in_sizes, int n_in,
                              void* d_out, int out_size)
{
    const float* query = (const float*)d_in[0];
    const float* w_in  = (const float*)d_in[1];
    const float* b_in  = (const float*)d_in[2];
    const float* w_out = (const float*)d_in[3];
    const float* b_out = (const float*)d_in[4];
    float* out = (float*)d_out;

    __half *p_qry16, *p_wih, *p_wil, *p_woh, *p_wol, *p_ctx16;
    cudaGetSymbolAddress((void**)&p_qry16, g_qry16);
    cudaGetSymbolAddress((void**)&p_wih, g_wih);
    cudaGetSymbolAddress((void**)&p_wil, g_wil);
    cudaGetSymbolAddress((void**)&p_woh, g_woh);
    cudaGetSymbolAddress((void**)&p_wol, g_wol);
    cudaGetSymbolAddress((void**)&p_ctx16, g_ctx16);

    cudaFuncSetAttribute(mma_gemm4<0>, cudaFuncAttributeMaxDynamicSharedMemorySize, GEMM_SMEM4);
    cudaFuncSetAttribute(mma_gemm4<1>, cudaFuncAttributeMaxDynamicSharedMemorySize, GEMM_SMEM4);
    cudaFuncSetAttribute(attn_mma3, cudaFuncAttributeMaxDynamicSharedMemorySize, ATTN_SMEM3);

    // 0) converts: query -> fp16; weights -> fp16 hi/lo
    cvt16_kernel<<<(TB * EE / 4 + 255) / 256, 256>>>(query, p_qry16, TB * EE / 4);
    split16_kernel<<<(FF * EE / 4 + 255) / 256, 256>>>(w_in, p_wih, p_wil, FF * EE / 4);
    split16_kernel<<<(EE * EE / 4 + 255) / 256, 256>>>(w_out, p_woh, p_wol, EE * EE / 4);

    // 1) QKV projection (fp16x2) -> q fp16 (scaled) / k,v hi/lo
    mma_gemm4<0><<<dim3(FF / 128, TB / 128), 256, GEMM_SMEM4>>>(p_qry16, p_wih, p_wil, b_in, nullptr);
    // 2) Flash attention (fp16x2) -> ctx fp16
    attn_mma3<<<dim3(TQ / 128, BB * HH), 256, ATTN_SMEM3>>>();
    // 3) Output projection (fp16x2) -> fp32 out
    mma_gemm4<1><<<dim3(EE / 128, TB / 128), 256, GEMM_SMEM4>>>(p_ctx16, p_woh, p_wol, b_out, out);
}

// round 11
// speedup vs baseline: 4.7546x; 1.0162x over previous
#include <cuda_runtime.h>
#include <cuda_fp16.h>
#include <math.h>
#include <cstdint>

// Problem constants
#define TQ 2048
#define BB 2
#define EE 1024
#define HH 16
#define DD 64
#define TB 4096          // TQ*BB
#define FF 3072          // 3*EE

#define QSCALE (0.125f * 1.44269504088896f)   // d^-0.5 * log2(e)  (softmax uses ex2)

// Scratch (allocation-free rule: __device__ globals)
__device__ __half g_qry16[(size_t)TB * EE];                       // A for gemm0 (fp16)
__device__ __half g_wih[(size_t)FF * EE], g_wil[(size_t)FF * EE]; // W_in hi/lo
__device__ __half g_woh[(size_t)EE * EE], g_wol[(size_t)EE * EE]; // W_out hi/lo
__device__ __half g_q16[(size_t)BB * HH * TQ * DD];               // Q fp16 (pre-scaled)
__device__ __half g_kh[(size_t)BB * HH * TQ * DD], g_kl[(size_t)BB * HH * TQ * DD];
__device__ __half g_vh[(size_t)BB * HH * TQ * DD], g_vl[(size_t)BB * HH * TQ * DD];
__device__ __half g_ctx16[(size_t)TB * EE];                       // A for gemm1 (fp16)

// ============================================================================
// helpers
// ============================================================================
__device__ __forceinline__ uint32_t smem_u32(const void* p) {
    uint32_t a;
    asm("{ .reg .u64 t; cvta.to.shared.u64 t, %1; cvt.u32.u64 %0, t; }" : "=r"(a) : "l"(p));
    return a;
}
__device__ __forceinline__ uint32_t cvt2h(float x, float y) {
    __half2 h = __floats2half2_rn(x, y);
    return *(uint32_t*)&h;
}
// split (x,y) into packed fp16 hi and lo words (x in low half)
__device__ __forceinline__ void split2h(float x, float y, uint32_t& hi, uint32_t& lo) {
    __half hx = __float2half_rn(x), hy = __float2half_rn(y);
    float rx = x - __half2float(hx), ry = y - __half2float(hy);
    __half2 h = __halves2half2(hx, hy);
    hi = *(uint32_t*)&h;
    lo = cvt2h(rx, ry);
}
__device__ __forceinline__ float ex2f(float x) {
    float y;
    asm("ex2.approx.f32 %0, %1;" : "=f"(y) : "f"(x));
    return y;
}
__device__ __forceinline__ void mma_f16(float* d, const uint32_t* a, const uint32_t* b) {
    asm volatile(
        "mma.sync.aligned.m16n8k16.row.col.f32.f16.f16.f32 "
        "{%0,%1,%2,%3}, {%4,%5,%6,%7}, {%8,%9}, {%0,%1,%2,%3};"
        : "+f"(d[0]), "+f"(d[1]), "+f"(d[2]), "+f"(d[3])
        : "r"(a[0]), "r"(a[1]), "r"(a[2]), "r"(a[3]), "r"(b[0]), "r"(b[1]));
}
#define LDSM_X4(R0,R1,R2,R3,ADDR) \
    asm volatile("ldmatrix.sync.aligned.m8n8.x4.shared.b16 {%0,%1,%2,%3}, [%4];" \
        : "=r"(R0), "=r"(R1), "=r"(R2), "=r"(R3) : "r"(ADDR))
#define LDSM_X4_T(R0,R1,R2,R3,ADDR) \
    asm volatile("ldmatrix.sync.aligned.m8n8.x4.trans.shared.b16 {%0,%1,%2,%3}, [%4];" \
        : "=r"(R0), "=r"(R1), "=r"(R2), "=r"(R3) : "r"(ADDR))
#define CP16(SM, GP) \
    asm volatile("cp.async.cg.shared.global [%0], [%1], 16;" :: "r"(SM), "l"(GP) : "memory")
#define CP_COMMIT() asm volatile("cp.async.commit_group;" ::: "memory")
#define CP_WAIT(N)  asm volatile("cp.async.wait_group %0;" :: "n"(N) : "memory")

// ============================================================================
// elementwise converters (HBM-bound, one-time)
// ============================================================================
__global__ void split16_kernel(const float* __restrict__ src,
                               __half* __restrict__ hi, __half* __restrict__ lo, int n4)
{
    int i = blockIdx.x * blockDim.x + threadIdx.x;
    if (i < n4) {
        float4 v = ((const float4*)src)[i];
        uint32_t h0, l0, h1, l1;
        split2h(v.x, v.y, h0, l0);
        split2h(v.z, v.w, h1, l1);
        ((uint2*)hi)[i] = make_uint2(h0, h1);
        ((uint2*)lo)[i] = make_uint2(l0, l1);
    }
}
__global__ void cvt16_kernel(const float* __restrict__ src, __half* __restrict__ dst, int n4)
{
    int i = blockIdx.x * blockDim.x + threadIdx.x;
    if (i < n4) {
        float4 v = ((const float4*)src)[i];
        ((uint2*)dst)[i] = make_uint2(cvt2h(v.x, v.y), cvt2h(v.z, v.w));
    }
}

// ============================================================================
// GEMM v5 (fp16x2): 256 threads, 128x128 CTA tile, warp tile 64x32,
// 4-stage cp.async, PAIR-COMMIT loop (one barrier per 2 K-chunks), 2 CTAs/SM.
// MODE 0: scatter q (fp16, scaled) / k,v (fp16 hi/lo). MODE 1: fp32 + bias.
// ============================================================================
#define GBK 32
#define GNC (EE / GBK)          // 32 chunks -> 16 pairs
#define GS_A  0
#define GS_BH 8192
#define GS_BL 16384
#define G_STAGE 24576
#define GEMM_SMEM5 (4 * G_STAGE)   // 98304

template <int MODE>
__global__ __launch_bounds__(256, 2)
void mma_gemm5(const __half* __restrict__ Ag,
               const __half* __restrict__ Bgh, const __half* __restrict__ Bgl,
               const float* __restrict__ bias, float* __restrict__ Cout)
{
    extern __shared__ char smem[];
    const uint32_t sb = smem_u32(smem);

    const int tid  = threadIdx.x;
    const int wid  = tid >> 5;
    const int lane = tid & 31;
    const int g    = lane >> 2;
    const int t    = lane & 3;
    const int wm   = (wid >> 2) << 6;   // 0 or 64
    const int wn   = (wid & 3) << 5;    // 0..96
    const int row0 = blockIdx.y * 128;
    const int col0 = blockIdx.x * 128;
    const int rK   = (lane & 7) + ((lane >> 4) & 1) * 8;
    const int cKb  = (lane >> 3) & 1;

    float acc[4][4][4];
#pragma unroll
    for (int i = 0; i < 4; i++)
#pragma unroll
        for (int j = 0; j < 4; j++)
#pragma unroll
            for (int k = 0; k < 4; k++) acc[i][j][k] = 0.0f;

    // copies of one chunk (no commit)
    auto issue_nc = [&](int c) {
        uint32_t st = sb + (uint32_t)(c & 3) * G_STAGE;
#pragma unroll
        for (int p = 0; p < 2; p++) {
            int id = tid + p * 256;
            int r  = id >> 2;
            int cg = id & 3;
            uint32_t so = (uint32_t)r * 64 + (uint32_t)((cg ^ ((r >> 1) & 3)) << 4);
            size_t ka = (size_t)(row0 + r) * EE + cg * 8 + (size_t)c * GBK;
            size_t kb = (size_t)(col0 + r) * EE + cg * 8 + (size_t)c * GBK;
            CP16(st + GS_A + so, Ag + ka);
            CP16(st + GS_BH + so, Bgh + kb);
            CP16(st + GS_BL + so, Bgl + kb);
        }
    };
    auto issue_pair = [&](int p) {
        issue_nc(2 * p);
        issue_nc(2 * p + 1);
        CP_COMMIT();
    };

    auto compute = [&](int c) {
        uint32_t base = sb + (uint32_t)(c & 3) * G_STAGE;
#pragma unroll
        for (int ks = 0; ks < 2; ks++) {
            uint32_t ah[4][4];
#pragma unroll
            for (int ma = 0; ma < 4; ma++) {
                int row  = wm + 16 * ma + (lane & 15);
                int cgrp = ks * 2 + (lane >> 4);
                uint32_t ad = base + GS_A + row * 64 + ((cgrp ^ ((row >> 1) & 3)) << 4);
                LDSM_X4(ah[ma][0], ah[ma][1], ah[ma][2], ah[ma][3], ad);
            }
            uint32_t bh2[4][2], bl2[4][2];
#pragma unroll
            for (int jj = 0; jj < 2; jj++) {
                int row  = wn + 16 * jj + rK;
                int cgrp = ks * 2 + cKb;
                uint32_t ad = base + GS_BH + row * 64 + ((cgrp ^ ((row >> 1) & 3)) << 4);
                LDSM_X4(bh2[2 * jj][0], bh2[2 * jj][1], bh2[2 * jj + 1][0], bh2[2 * jj + 1][1], ad);
                LDSM_X4(bl2[2 * jj][0], bl2[2 * jj][1], bl2[2 * jj + 1][0], bl2[2 * jj + 1][1], ad + 8192);
            }
#pragma unroll
            for (int ma = 0; ma < 4; ma++)
#pragma unroll
                for (int na = 0; na < 4; na++) mma_f16(acc[ma][na], ah[ma], bh2[na]);
#pragma unroll
            for (int ma = 0; ma < 4; ma++)
#pragma unroll
                for (int na = 0; na < 4; na++) mma_f16(acc[ma][na], ah[ma], bl2[na]);
        }
    };

    // ---- pair-commit main loop: one barrier per 2 chunks ----
    issue_pair(0);
    for (int p = 0; p < GNC / 2; p++) {
        CP_WAIT(0);            // pair p landed (this thread's copies)
        __syncthreads();       // visibility of all threads' copies + stage reuse guard
        if (p + 1 < GNC / 2) issue_pair(p + 1);   // overlaps compute of pair p
        compute(2 * p);
        compute(2 * p + 1);
    }

    // ---- epilogue ----
#pragma unroll
    for (int na = 0; na < 4; na++) {
        const int f0 = col0 + wn + 8 * na + 2 * t;
        const float b0 = bias[f0];
        const float b1 = bias[f0 + 1];
        if (MODE == 0) {
            int h     = f0 / 192;
            int rem   = f0 - 192 * h;
            int which = rem >> 6;
            int dd    = rem & 63;
#pragma unroll
            for (int ma = 0; ma < 4; ma++) {
                const float* d4 = acc[ma][na];
                int tb = row0 + wm + 16 * ma + g;
#pragma unroll
                for (int hh = 0; hh < 2; hh++) {
                    int tbx = tb + 8 * hh;
                    int tt = tbx >> 1, bb = tbx & 1;
                    size_t off = ((size_t)(bb * HH + h) * TQ + tt) * DD + dd;
                    float x = d4[2 * hh] + b0, y = d4[2 * hh + 1] + b1;
                    if (which == 0) {
                        *(uint32_t*)(g_q16 + off) = cvt2h(x * QSCALE, y * QSCALE);
                    } else {
                        __half* dh = (which == 1) ? g_kh : g_vh;
                        __half* dl = (which == 1) ? g_kl : g_vl;
                        uint32_t hi, lo;
                        split2h(x, y, hi, lo);
                        *(uint32_t*)(dh + off) = hi;
                        *(uint32_t*)(dl + off) = lo;
                    }
                }
            }
        } else {
#pragma unroll
            for (int ma = 0; ma < 4; ma++) {
                const float* d4 = acc[ma][na];
                int r = row0 + wm + 16 * ma + g;
                *(float2*)(Cout + (size_t)r * EE + f0) = make_float2(d4[0] + b0, d4[1] + b1);
                *(float2*)(Cout + (size_t)(r + 8) * EE + f0) = make_float2(d4[2] + b0, d4[3] + b1);
            }
        }
    }
}

// ============================================================================
// Flash attention v4 (fp16x2): Q fp16 single, K/V hi/lo, 3-stage KV ring with
// Q-overlay (Q smem reused as stage 0 after fragment load), CP_WAIT(1).
// CTA: 128 q-rows of one (b,h), 8 warps x 16 rows, KV tiles of 64. 2 CTAs/SM.
// FIX vs r9: __syncthreads() between CP_WAIT and Q-fragment ldmatrix
// (cp.async wait_group is per-thread; cross-thread visibility needs a barrier).
// ============================================================================
#define AKV_ST4 32768              // per stage: KH 0, KL 8192, VH 16384, VL 24576
#define ATTN_SMEM4 (3 * AKV_ST4)   // 98304 ; Q overlays stage 0 (first 16KB)
#define NTILES (TQ / 64)           // 32

__global__ __launch_bounds__(256, 2)
void attn_mma4()
{
    extern __shared__ char sm[];
    const uint32_t sb = smem_u32(sm);

    const int tid  = threadIdx.x;
    const int wid  = tid >> 5;
    const int lane = tid & 31;
    const int g    = lane >> 2;
    const int t    = lane & 3;

    const int bh = blockIdx.y;
    const int b  = bh >> 4;
    const int h  = bh & 15;
    const size_t base = (size_t)bh * TQ * DD;
    const int t0 = blockIdx.x * 128;
    const int m0 = wid * 16;

    const int rK  = (lane & 7) + ((lane >> 4) & 1) * 8;
    const int cKb = (lane >> 3) & 1;
    const int rV  = (lane & 7) + ((lane >> 3) & 1) * 8;
    const int cVb = (lane >> 4) & 1;

    // stage(tile j) = (j+1) % 3
    auto issueQ = [&]() {   // into [0, 16K) = start of stage 0
#pragma unroll
        for (int p = 0; p < 4; p++) {
            int id = tid + p * 256;
            int r = id >> 3, cgp = id & 7;
            uint32_t so = (uint32_t)r * 128 + ((cgp ^ (r & 7)) << 4);
            CP16(sb + so, g_q16 + base + (size_t)(t0 + r) * DD + cgp * 8);
        }
        CP_COMMIT();
    };
    auto issueKV = [&](int st, int stage) {
        uint32_t kvb = sb + (uint32_t)stage * AKV_ST4;
#pragma unroll
        for (int p = 0; p < 2; p++) {
            int id = tid + p * 256;
            int r = id >> 3, cgp = id & 7;
            uint32_t so = (uint32_t)r * 128 + ((cgp ^ (r & 7)) << 4);
            size_t go = base + (size_t)(st + r) * DD + cgp * 8;
            CP16(kvb + so,         g_kh + go);
            CP16(kvb + 8192 + so,  g_kl + go);
            CP16(kvb + 16384 + so, g_vh + go);
            CP16(kvb + 24576 + so, g_vl + go);
        }
        CP_COMMIT();
    };

    issueQ();
    issueKV(0, 1);
    issueKV(64, 2);
    CP_WAIT(2);           // this thread's Q copies landed (tiles 0,1 may be in flight)
    __syncthreads();      // FIX: make ALL threads' Q copies visible before ldmatrix

    // ---- Q fragments (persistent, fp16 single) ----
    uint32_t qh[4][4];
    {
        int row = m0 + (lane & 15);
#pragma unroll
        for (int ks = 0; ks < 4; ks++) {
            int cgrp = ks * 2 + (lane >> 4);
            uint32_t a = sb + row * 128 + ((cgrp ^ (row & 7)) << 4);
            LDSM_X4(qh[ks][0], qh[ks][1], qh[ks][2], qh[ks][3], a);
        }
    }
    __syncthreads();      // all warps done reading Q; stage 0 reusable

    float O[8][4];
#pragma unroll
    for (int j = 0; j < 8; j++)
#pragma unroll
        for (int k = 0; k < 4; k++) O[j][k] = 0.0f;
    float mrow0 = -1e30f, mrow1 = -1e30f, lrow0 = 0.0f, lrow1 = 0.0f;

    for (int i = 0; i < NTILES; i++) {
        if (i + 1 < NTILES) { CP_WAIT(1); } else { CP_WAIT(0); }  // tile i landed
        __syncthreads();                      // visibility + stage-reuse guard
        if (i + 2 < NTILES) issueKV((i + 2) * 64, (i + 3) % 3);

        uint32_t kvb = sb + (uint32_t)((i + 1) % 3) * AKV_ST4;

        // ---- S = Q K^T (2-pass) ----
        float S[8][4];
#pragma unroll
        for (int j = 0; j < 8; j++)
#pragma unroll
            for (int k = 0; k < 4; k++) S[j][k] = 0.0f;

#pragma unroll
        for (int ks = 0; ks < 4; ks++) {
            uint32_t bh_[8][2], bl_[8][2];
#pragma unroll
            for (int jj = 0; jj < 4; jj++) {
                int row  = 16 * jj + rK;
                int cgrp = ks * 2 + cKb;
                uint32_t a = kvb + row * 128 + ((cgrp ^ (row & 7)) << 4);
                LDSM_X4(bh_[2 * jj][0], bh_[2 * jj][1], bh_[2 * jj + 1][0], bh_[2 * jj + 1][1], a);
                LDSM_X4(bl_[2 * jj][0], bl_[2 * jj][1], bl_[2 * jj + 1][0], bl_[2 * jj + 1][1], a + 8192);
            }
#pragma unroll
            for (int j = 0; j < 8; j++) mma_f16(S[j], qh[ks], bh_[j]);
#pragma unroll
            for (int j = 0; j < 8; j++) mma_f16(S[j], qh[ks], bl_[j]);
        }

        // ---- online softmax (base-2) ----
        float mx0 = -1e30f, mx1 = -1e30f;
#pragma unroll
        for (int j = 0; j < 8; j++) {
            mx0 = fmaxf(mx0, fmaxf(S[j][0], S[j][1]));
            mx1 = fmaxf(mx1, fmaxf(S[j][2], S[j][3]));
        }
        mx0 = fmaxf(mx0, __shfl_xor_sync(0xffffffffu, mx0, 1));
        mx0 = fmaxf(mx0, __shfl_xor_sync(0xffffffffu, mx0, 2));
        mx1 = fmaxf(mx1, __shfl_xor_sync(0xffffffffu, mx1, 1));
        mx1 = fmaxf(mx1, __shfl_xor_sync(0xffffffffu, mx1, 2));
        float mn0 = fmaxf(mrow0, mx0), mn1 = fmaxf(mrow1, mx1);
        float sc0 = ex2f(mrow0 - mn0), sc1 = ex2f(mrow1 - mn1);
        float s0 = 0.0f, s1 = 0.0f;
#pragma unroll
        for (int j = 0; j < 8; j++) {
            S[j][0] = ex2f(S[j][0] - mn0);
            S[j][1] = ex2f(S[j][1] - mn0);
            S[j][2] = ex2f(S[j][2] - mn1);
            S[j][3] = ex2f(S[j][3] - mn1);
            s0 += S[j][0] + S[j][1];
            s1 += S[j][2] + S[j][3];
        }
        s0 += __shfl_xor_sync(0xffffffffu, s0, 1);
        s0 += __shfl_xor_sync(0xffffffffu, s0, 2);
        s1 += __shfl_xor_sync(0xffffffffu, s1, 1);
        s1 += __shfl_xor_sync(0xffffffffu, s1, 2);
        lrow0 = lrow0 * sc0 + s0;
        lrow1 = lrow1 * sc1 + s1;
        mrow0 = mn0;
        mrow1 = mn1;
#pragma unroll
        for (int j = 0; j < 8; j++) {
            O[j][0] *= sc0; O[j][1] *= sc0;
            O[j][2] *= sc1; O[j][3] *= sc1;
        }

        // ---- P fragments (fp16 single, straight from S accumulators) ----
        uint32_t ph[4][4];
#pragma unroll
        for (int kk = 0; kk < 4; kk++) {
            ph[kk][0] = cvt2h(S[2 * kk][0],     S[2 * kk][1]);
            ph[kk][1] = cvt2h(S[2 * kk][2],     S[2 * kk][3]);
            ph[kk][2] = cvt2h(S[2 * kk + 1][0], S[2 * kk + 1][1]);
            ph[kk][3] = cvt2h(S[2 * kk + 1][2], S[2 * kk + 1][3]);
        }

        // ---- O += P V (2-pass) ----
#pragma unroll
        for (int kk = 0; kk < 4; kk++) {
            uint32_t vh_[8][2], vl_[8][2];
#pragma unroll
            for (int jj = 0; jj < 4; jj++) {
                int row  = kk * 16 + rV;
                int cgrp = jj * 2 + cVb;
                uint32_t a = kvb + 16384 + row * 128 + ((cgrp ^ (row & 7)) << 4);
                LDSM_X4_T(vh_[2 * jj][0], vh_[2 * jj][1], vh_[2 * jj + 1][0], vh_[2 * jj + 1][1], a);
                LDSM_X4_T(vl_[2 * jj][0], vl_[2 * jj][1], vl_[2 * jj + 1][0], vl_[2 * jj + 1][1], a + 8192);
            }
#pragma unroll
            for (int j = 0; j < 8; j++) mma_f16(O[j], ph[kk], vh_[j]);
#pragma unroll
            for (int j = 0; j < 8; j++) mma_f16(O[j], ph[kk], vl_[j]);
        }
    }

    // ---- epilogue: ctx fp16 single, layout [TB, EE] ----
    float inv0 = 1.0f / lrow0, inv1 = 1.0f / lrow1;
    int qr0 = t0 + m0 + g;
    int qr1 = qr0 + 8;
#pragma unroll
    for (int j = 0; j < 8; j++) {
        int col = h * 64 + 8 * j + 2 * t;
        *(uint32_t*)(g_ctx16 + (size_t)(qr0 * BB + b) * EE + col) =
            cvt2h(O[j][0] * inv0, O[j][1] * inv0);
        *(uint32_t*)(g_ctx16 + (size_t)(qr1 * BB + b) * EE + col) =
            cvt2h(O[j][2] * inv1, O[j][3] * inv1);
    }
}

// ============================================================================
// Launch
// ============================================================================
extern "C" void kernel_launch(void* const* d_in, const int* in_sizes, int n_in,
                              void* d_out, int out_size)
{
    const float* query = (const float*)d_in[0];
    const float* w_in  = (const float*)d_in[1];
    const float* b_in  = (const float*)d_in[2];
    const float* w_out = (const float*)d_in[3];
    const float* b_out = (const float*)d_in[4];
    float* out = (float*)d_out;

    __half *p_qry16, *p_wih, *p_wil, *p_woh, *p_wol, *p_ctx16;
    cudaGetSymbolAddress((void**)&p_qry16, g_qry16);
    cudaGetSymbolAddress((void**)&p_wih, g_wih);
    cudaGetSymbolAddress((void**)&p_wil, g_wil);
    cudaGetSymbolAddress((void**)&p_woh, g_woh);
    cudaGetSymbolAddress((void**)&p_wol, g_wol);
    cudaGetSymbolAddress((void**)&p_ctx16, g_ctx16);

    cudaFuncSetAttribute(mma_gemm5<0>, cudaFuncAttributeMaxDynamicSharedMemorySize, GEMM_SMEM5);
    cudaFuncSetAttribute(mma_gemm5<1>, cudaFuncAttributeMaxDynamicSharedMemorySize, GEMM_SMEM5);
    cudaFuncSetAttribute(attn_mma4, cudaFuncAttributeMaxDynamicSharedMemorySize, ATTN_SMEM4);

    // 0) converts: query -> fp16; weights -> fp16 hi/lo
    cvt16_kernel<<<(TB * EE / 4 + 255) / 256, 256>>>(query, p_qry16, TB * EE / 4);
    split16_kernel<<<(FF * EE / 4 + 255) / 256, 256>>>(w_in, p_wih, p_wil, FF * EE / 4);
    split16_kernel<<<(EE * EE / 4 + 255) / 256, 256>>>(w_out, p_woh, p_wol, EE * EE / 4);

    // 1) QKV projection (fp16x2) -> q fp16 (scaled) / k,v hi/lo
    mma_gemm5<0><<<dim3(FF / 128, TB / 128), 256, GEMM_SMEM5>>>(p_qry16, p_wih, p_wil, b_in, nullptr);
    // 2) Flash attention (fp16x2) -> ctx fp16
    attn_mma4<<<dim3(TQ / 128, BB * HH), 256, ATTN_SMEM4>>>();
    // 3) Output projection (fp16x2) -> fp32 out
    mma_gemm5<1><<<dim3(EE / 128, TB / 128), 256, GEMM_SMEM5>>>(p_ctx16, p_woh, p_wol, b_out, out);
}

// round 13
// speedup vs baseline: 5.8719x; 1.2350x over previous
#include <cuda_runtime.h>
#include <cuda_fp16.h>
#include <math.h>
#include <cstdint>

// Problem constants
#define TQ 2048
#define BB 2
#define EE 1024
#define HH 16
#define DD 64
#define TB 4096          // TQ*BB
#define FF 3072          // 3*EE

#define QSCALE (0.125f * 1.44269504088896f)   // d^-0.5 * log2(e)  (softmax uses ex2)

// Scratch (allocation-free rule: __device__ globals)
__device__ __half g_qry16[(size_t)TB * EE];                       // A for gemm0 (fp16)
__device__ __half g_wih[(size_t)FF * EE], g_wil[(size_t)FF * EE]; // W_in hi/lo
__device__ __half g_woh[(size_t)EE * EE], g_wol[(size_t)EE * EE]; // W_out hi/lo
__device__ __half g_q16[(size_t)BB * HH * TQ * DD];               // Q fp16 (pre-scaled)
__device__ __half g_k16[(size_t)BB * HH * TQ * DD];               // K fp16 single
__device__ __half g_v16[(size_t)BB * HH * TQ * DD];               // V fp16 single
__device__ __half g_ctx16[(size_t)TB * EE];                       // A for gemm1 (fp16)

// ============================================================================
// helpers
// ============================================================================
__device__ __forceinline__ uint32_t smem_u32(const void* p) {
    uint32_t a;
    asm("{ .reg .u64 t; cvta.to.shared.u64 t, %1; cvt.u32.u64 %0, t; }" : "=r"(a) : "l"(p));
    return a;
}
__device__ __forceinline__ uint32_t cvt2h(float x, float y) {
    __half2 h = __floats2half2_rn(x, y);
    return *(uint32_t*)&h;
}
// split (x,y) into packed fp16 hi and lo words (x in low half)
__device__ __forceinline__ void split2h(float x, float y, uint32_t& hi, uint32_t& lo) {
    __half hx = __float2half_rn(x), hy = __float2half_rn(y);
    float rx = x - __half2float(hx), ry = y - __half2float(hy);
    __half2 h = __halves2half2(hx, hy);
    hi = *(uint32_t*)&h;
    lo = cvt2h(rx, ry);
}
__device__ __forceinline__ float ex2f(float x) {
    float y;
    asm("ex2.approx.f32 %0, %1;" : "=f"(y) : "f"(x));
    return y;
}
__device__ __forceinline__ void mma_f16(float* d, const uint32_t* a, const uint32_t* b) {
    asm volatile(
        "mma.sync.aligned.m16n8k16.row.col.f32.f16.f16.f32 "
        "{%0,%1,%2,%3}, {%4,%5,%6,%7}, {%8,%9}, {%0,%1,%2,%3};"
        : "+f"(d[0]), "+f"(d[1]), "+f"(d[2]), "+f"(d[3])
        : "r"(a[0]), "r"(a[1]), "r"(a[2]), "r"(a[3]), "r"(b[0]), "r"(b[1]));
}
#define LDSM_X4(R0,R1,R2,R3,ADDR) \
    asm volatile("ldmatrix.sync.aligned.m8n8.x4.shared.b16 {%0,%1,%2,%3}, [%4];" \
        : "=r"(R0), "=r"(R1), "=r"(R2), "=r"(R3) : "r"(ADDR))
#define LDSM_X4_T(R0,R1,R2,R3,ADDR) \
    asm volatile("ldmatrix.sync.aligned.m8n8.x4.trans.shared.b16 {%0,%1,%2,%3}, [%4];" \
        : "=r"(R0), "=r"(R1), "=r"(R2), "=r"(R3) : "r"(ADDR))
#define CP16(SM, GP) \
    asm volatile("cp.async.cg.shared.global [%0], [%1], 16;" :: "r"(SM), "l"(GP) : "memory")
#define CP_COMMIT() asm volatile("cp.async.commit_group;" ::: "memory")
#define CP_WAIT(N)  asm volatile("cp.async.wait_group %0;" :: "n"(N) : "memory")

// ============================================================================
// elementwise converters (HBM-bound, one-time)
// ============================================================================
__global__ void split16_kernel(const float* __restrict__ src,
                               __half* __restrict__ hi, __half* __restrict__ lo, int n4)
{
    int i = blockIdx.x * blockDim.x + threadIdx.x;
    if (i < n4) {
        float4 v = ((const float4*)src)[i];
        uint32_t h0, l0, h1, l1;
        split2h(v.x, v.y, h0, l0);
        split2h(v.z, v.w, h1, l1);
        ((uint2*)hi)[i] = make_uint2(h0, h1);
        ((uint2*)lo)[i] = make_uint2(l0, l1);
    }
}
__global__ void cvt16_kernel(const float* __restrict__ src, __half* __restrict__ dst, int n4)
{
    int i = blockIdx.x * blockDim.x + threadIdx.x;
    if (i < n4) {
        float4 v = ((const float4*)src)[i];
        ((uint2*)dst)[i] = make_uint2(cvt2h(v.x, v.y), cvt2h(v.z, v.w));
    }
}

// ============================================================================
// GEMM v5 (fp16x2): 256 threads, 128x128 CTA tile, warp tile 64x32,
// 4-stage cp.async, pair-commit loop, 2 CTAs/SM.
// MODE 0: scatter q/k/v (fp16 single, q scaled). MODE 1: fp32 + bias.
// ============================================================================
#define GBK 32
#define GNC (EE / GBK)          // 32 chunks -> 16 pairs
#define GS_A  0
#define GS_BH 8192
#define GS_BL 16384
#define G_STAGE 24576
#define GEMM_SMEM5 (4 * G_STAGE)   // 98304

template <int MODE>
__global__ __launch_bounds__(256, 2)
void mma_gemm5(const __half* __restrict__ Ag,
               const __half* __restrict__ Bgh, const __half* __restrict__ Bgl,
               const float* __restrict__ bias, float* __restrict__ Cout)
{
    extern __shared__ char smem[];
    const uint32_t sb = smem_u32(smem);

    const int tid  = threadIdx.x;
    const int wid  = tid >> 5;
    const int lane = tid & 31;
    const int g    = lane >> 2;
    const int t    = lane & 3;
    const int wm   = (wid >> 2) << 6;   // 0 or 64
    const int wn   = (wid & 3) << 5;    // 0..96
    const int row0 = blockIdx.y * 128;
    const int col0 = blockIdx.x * 128;
    const int rK   = (lane & 7) + ((lane >> 4) & 1) * 8;
    const int cKb  = (lane >> 3) & 1;

    float acc[4][4][4];
#pragma unroll
    for (int i = 0; i < 4; i++)
#pragma unroll
        for (int j = 0; j < 4; j++)
#pragma unroll
            for (int k = 0; k < 4; k++) acc[i][j][k] = 0.0f;

    // copies of one chunk (no commit)
    auto issue_nc = [&](int c) {
        uint32_t st = sb + (uint32_t)(c & 3) * G_STAGE;
#pragma unroll
        for (int p = 0; p < 2; p++) {
            int id = tid + p * 256;
            int r  = id >> 2;
            int cg = id & 3;
            uint32_t so = (uint32_t)r * 64 + (uint32_t)((cg ^ ((r >> 1) & 3)) << 4);
            size_t ka = (size_t)(row0 + r) * EE + cg * 8 + (size_t)c * GBK;
            size_t kb = (size_t)(col0 + r) * EE + cg * 8 + (size_t)c * GBK;
            CP16(st + GS_A + so, Ag + ka);
            CP16(st + GS_BH + so, Bgh + kb);
            CP16(st + GS_BL + so, Bgl + kb);
        }
    };
    auto issue_pair = [&](int p) {
        issue_nc(2 * p);
        issue_nc(2 * p + 1);
        CP_COMMIT();
    };

    auto compute = [&](int c) {
        uint32_t base = sb + (uint32_t)(c & 3) * G_STAGE;
#pragma unroll
        for (int ks = 0; ks < 2; ks++) {
            uint32_t ah[4][4];
#pragma unroll
            for (int ma = 0; ma < 4; ma++) {
                int row  = wm + 16 * ma + (lane & 15);
                int cgrp = ks * 2 + (lane >> 4);
                uint32_t ad = base + GS_A + row * 64 + ((cgrp ^ ((row >> 1) & 3)) << 4);
                LDSM_X4(ah[ma][0], ah[ma][1], ah[ma][2], ah[ma][3], ad);
            }
            uint32_t bh2[4][2], bl2[4][2];
#pragma unroll
            for (int jj = 0; jj < 2; jj++) {
                int row  = wn + 16 * jj + rK;
                int cgrp = ks * 2 + cKb;
                uint32_t ad = base + GS_BH + row * 64 + ((cgrp ^ ((row >> 1) & 3)) << 4);
                LDSM_X4(bh2[2 * jj][0], bh2[2 * jj][1], bh2[2 * jj + 1][0], bh2[2 * jj + 1][1], ad);
                LDSM_X4(bl2[2 * jj][0], bl2[2 * jj][1], bl2[2 * jj + 1][0], bl2[2 * jj + 1][1], ad + 8192);
            }
#pragma unroll
            for (int ma = 0; ma < 4; ma++)
#pragma unroll
                for (int na = 0; na < 4; na++) mma_f16(acc[ma][na], ah[ma], bh2[na]);
#pragma unroll
            for (int ma = 0; ma < 4; ma++)
#pragma unroll
                for (int na = 0; na < 4; na++) mma_f16(acc[ma][na], ah[ma], bl2[na]);
        }
    };

    // ---- pair-commit main loop: one barrier per 2 chunks ----
    issue_pair(0);
    for (int p = 0; p < GNC / 2; p++) {
        CP_WAIT(0);            // pair p landed (this thread's copies)
        __syncthreads();       // visibility of all threads' copies + stage reuse guard
        if (p + 1 < GNC / 2) issue_pair(p + 1);   // overlaps compute of pair p
        compute(2 * p);
        compute(2 * p + 1);
    }

    // ---- epilogue ----
#pragma unroll
    for (int na = 0; na < 4; na++) {
        const int f0 = col0 + wn + 8 * na + 2 * t;
        const float b0 = bias[f0];
        const float b1 = bias[f0 + 1];
        if (MODE == 0) {
            int h     = f0 / 192;
            int rem   = f0 - 192 * h;
            int which = rem >> 6;
            int dd    = rem & 63;
            __half* dst = (which == 0) ? g_q16 : ((which == 1) ? g_k16 : g_v16);
            float mul = (which == 0) ? QSCALE : 1.0f;
#pragma unroll
            for (int ma = 0; ma < 4; ma++) {
                const float* d4 = acc[ma][na];
                int tb = row0 + wm + 16 * ma + g;
#pragma unroll
                for (int hh = 0; hh < 2; hh++) {
                    int tbx = tb + 8 * hh;
                    int tt = tbx >> 1, bb = tbx & 1;
                    size_t off = ((size_t)(bb * HH + h) * TQ + tt) * DD + dd;
                    *(uint32_t*)(dst + off) =
                        cvt2h((d4[2 * hh] + b0) * mul, (d4[2 * hh + 1] + b1) * mul);
                }
            }
        } else {
#pragma unroll
            for (int ma = 0; ma < 4; ma++) {
                const float* d4 = acc[ma][na];
                int r = row0 + wm + 16 * ma + g;
                *(float2*)(Cout + (size_t)r * EE + f0) = make_float2(d4[0] + b0, d4[1] + b1);
                *(float2*)(Cout + (size_t)(r + 8) * EE + f0) = make_float2(d4[2] + b0, d4[3] + b1);
            }
        }
    }
}

// ============================================================================
// Flash attention v5 (pure fp16 operands): Q/K/V/P all single fp16, fp32 accum.
// 3-stage KV ring (16KB/stage: K at +0, V at +8192), Q overlays stage 0.
// CTA: 128 q-rows of one (b,h), 8 warps x 16 rows, KV tiles of 64. 2 CTAs/SM.
// ============================================================================
#define AKV_ST5 16384              // per stage: K 0..8K, V 8K..16K
#define ATTN_SMEM5 (3 * AKV_ST5)   // 49152 ; Q (16KB) overlays stage 0 exactly
#define NTILES (TQ / 64)           // 32

__global__ __launch_bounds__(256, 2)
void attn_mma5()
{
    extern __shared__ char sm[];
    const uint32_t sb = smem_u32(sm);

    const int tid  = threadIdx.x;
    const int wid  = tid >> 5;
    const int lane = tid & 31;
    const int g    = lane >> 2;
    const int t    = lane & 3;

    const int bh = blockIdx.y;
    const int b  = bh >> 4;
    const int h  = bh & 15;
    const size_t base = (size_t)bh * TQ * DD;
    const int t0 = blockIdx.x * 128;
    const int m0 = wid * 16;

    const int rK  = (lane & 7) + ((lane >> 4) & 1) * 8;
    const int cKb = (lane >> 3) & 1;
    const int rV  = (lane & 7) + ((lane >> 3) & 1) * 8;
    const int cVb = (lane >> 4) & 1;

    // stage(tile j) = (j+1) % 3
    auto issueQ = [&]() {   // into [0, 16K) = stage 0
#pragma unroll
        for (int p = 0; p < 4; p++) {
            int id = tid + p * 256;
            int r = id >> 3, cgp = id & 7;
            uint32_t so = (uint32_t)r * 128 + ((cgp ^ (r & 7)) << 4);
            CP16(sb + so, g_q16 + base + (size_t)(t0 + r) * DD + cgp * 8);
        }
        CP_COMMIT();
    };
    auto issueKV = [&](int st, int stage) {
        uint32_t kvb = sb + (uint32_t)stage * AKV_ST5;
#pragma unroll
        for (int p = 0; p < 2; p++) {
            int id = tid + p * 256;
            int r = id >> 3, cgp = id & 7;
            uint32_t so = (uint32_t)r * 128 + ((cgp ^ (r & 7)) << 4);
            size_t go = base + (size_t)(st + r) * DD + cgp * 8;
            CP16(kvb + so,        g_k16 + go);
            CP16(kvb + 8192 + so, g_v16 + go);
        }
        CP_COMMIT();
    };

    issueQ();
    issueKV(0, 1);
    issueKV(64, 2);
    CP_WAIT(2);           // this thread's Q copies landed
    __syncthreads();      // make ALL threads' Q copies visible before ldmatrix

    // ---- Q fragments (persistent, fp16 single) ----
    uint32_t qh[4][4];
    {
        int row = m0 + (lane & 15);
#pragma unroll
        for (int ks = 0; ks < 4; ks++) {
            int cgrp = ks * 2 + (lane >> 4);
            uint32_t a = sb + row * 128 + ((cgrp ^ (row & 7)) << 4);
            LDSM_X4(qh[ks][0], qh[ks][1], qh[ks][2], qh[ks][3], a);
        }
    }
    __syncthreads();      // all warps done reading Q; stage 0 reusable

    float O[8][4];
#pragma unroll
    for (int j = 0; j < 8; j++)
#pragma unroll
        for (int k = 0; k < 4; k++) O[j][k] = 0.0f;
    float mrow0 = -1e30f, mrow1 = -1e30f, lrow0 = 0.0f, lrow1 = 0.0f;

    for (int i = 0; i < NTILES; i++) {
        if (i + 1 < NTILES) { CP_WAIT(1); } else { CP_WAIT(0); }  // tile i landed
        __syncthreads();                      // visibility + stage-reuse guard
        if (i + 2 < NTILES) issueKV((i + 2) * 64, (i + 3) % 3);

        uint32_t kvb = sb + (uint32_t)((i + 1) % 3) * AKV_ST5;

        // ---- S = Q K^T (single pass) ----
        float S[8][4];
#pragma unroll
        for (int j = 0; j < 8; j++)
#pragma unroll
            for (int k = 0; k < 4; k++) S[j][k] = 0.0f;

#pragma unroll
        for (int ks = 0; ks < 4; ks++) {
            uint32_t bh_[8][2];
#pragma unroll
            for (int jj = 0; jj < 4; jj++) {
                int row  = 16 * jj + rK;
                int cgrp = ks * 2 + cKb;
                uint32_t a = kvb + row * 128 + ((cgrp ^ (row & 7)) << 4);
                LDSM_X4(bh_[2 * jj][0], bh_[2 * jj][1], bh_[2 * jj + 1][0], bh_[2 * jj + 1][1], a);
            }
#pragma unroll
            for (int j = 0; j < 8; j++) mma_f16(S[j], qh[ks], bh_[j]);
        }

        // ---- online softmax (base-2) ----
        float mx0 = -1e30f, mx1 = -1e30f;
#pragma unroll
        for (int j = 0; j < 8; j++) {
            mx0 = fmaxf(mx0, fmaxf(S[j][0], S[j][1]));
            mx1 = fmaxf(mx1, fmaxf(S[j][2], S[j][3]));
        }
        mx0 = fmaxf(mx0, __shfl_xor_sync(0xffffffffu, mx0, 1));
        mx0 = fmaxf(mx0, __shfl_xor_sync(0xffffffffu, mx0, 2));
        mx1 = fmaxf(mx1, __shfl_xor_sync(0xffffffffu, mx1, 1));
        mx1 = fmaxf(mx1, __shfl_xor_sync(0xffffffffu, mx1, 2));
        float mn0 = fmaxf(mrow0, mx0), mn1 = fmaxf(mrow1, mx1);
        float sc0 = ex2f(mrow0 - mn0), sc1 = ex2f(mrow1 - mn1);
        float s0 = 0.0f, s1 = 0.0f;
#pragma unroll
        for (int j = 0; j < 8; j++) {
            S[j][0] = ex2f(S[j][0] - mn0);
            S[j][1] = ex2f(S[j][1] - mn0);
            S[j][2] = ex2f(S[j][2] - mn1);
            S[j][3] = ex2f(S[j][3] - mn1);
            s0 += S[j][0] + S[j][1];
            s1 += S[j][2] + S[j][3];
        }
        s0 += __shfl_xor_sync(0xffffffffu, s0, 1);
        s0 += __shfl_xor_sync(0xffffffffu, s0, 2);
        s1 += __shfl_xor_sync(0xffffffffu, s1, 1);
        s1 += __shfl_xor_sync(0xffffffffu, s1, 2);
        lrow0 = lrow0 * sc0 + s0;
        lrow1 = lrow1 * sc1 + s1;
        mrow0 = mn0;
        mrow1 = mn1;
#pragma unroll
        for (int j = 0; j < 8; j++) {
            O[j][0] *= sc0; O[j][1] *= sc0;
            O[j][2] *= sc1; O[j][3] *= sc1;
        }

        // ---- P fragments (fp16 single, straight from S accumulators) ----
        uint32_t ph[4][4];
#pragma unroll
        for (int kk = 0; kk < 4; kk++) {
            ph[kk][0] = cvt2h(S[2 * kk][0],     S[2 * kk][1]);
            ph[kk][1] = cvt2h(S[2 * kk][2],     S[2 * kk][3]);
            ph[kk][2] = cvt2h(S[2 * kk + 1][0], S[2 * kk + 1][1]);
            ph[kk][3] = cvt2h(S[2 * kk + 1][2], S[2 * kk + 1][3]);
        }

        // ---- O += P V (single pass) ----
#pragma unroll
        for (int kk = 0; kk < 4; kk++) {
            uint32_t vh_[8][2];
#pragma unroll
            for (int jj = 0; jj < 4; jj++) {
                int row  = kk * 16 + rV;
                int cgrp = jj * 2 + cVb;
                uint32_t a = kvb + 8192 + row * 128 + ((cgrp ^ (row & 7)) << 4);
                LDSM_X4_T(vh_[2 * jj][0], vh_[2 * jj][1], vh_[2 * jj + 1][0], vh_[2 * jj + 1][1], a);
            }
#pragma unroll
            for (int j = 0; j < 8; j++) mma_f16(O[j], ph[kk], vh_[j]);
        }
    }

    // ---- epilogue: ctx fp16 single, layout [TB, EE] ----
    float inv0 = 1.0f / lrow0, inv1 = 1.0f / lrow1;
    int qr0 = t0 + m0 + g;
    int qr1 = qr0 + 8;
#pragma unroll
    for (int j = 0; j < 8; j++) {
        int col = h * 64 + 8 * j + 2 * t;
        *(uint32_t*)(g_ctx16 + (size_t)(qr0 * BB + b) * EE + col) =
            cvt2h(O[j][0] * inv0, O[j][1] * inv0);
        *(uint32_t*)(g_ctx16 + (size_t)(qr1 * BB + b) * EE + col) =
            cvt2h(O[j][2] * inv1, O[j][3] * inv1);
    }
}

// ============================================================================
// Launch
// ============================================================================
extern "C" void kernel_launch(void* const* d_in, const int* in_sizes, int n_in,
                              void* d_out, int out_size)
{
    const float* query = (const float*)d_in[0];
    const float* w_in  = (const float*)d_in[1];
    const float* b_in  = (const float*)d_in[2];
    const float* w_out = (const float*)d_in[3];
    const float* b_out = (const float*)d_in[4];
    float* out = (float*)d_out;

    __half *p_qry16, *p_wih, *p_wil, *p_woh, *p_wol, *p_ctx16;
    cudaGetSymbolAddress((void**)&p_qry16, g_qry16);
    cudaGetSymbolAddress((void**)&p_wih, g_wih);
    cudaGetSymbolAddress((void**)&p_wil, g_wil);
    cudaGetSymbolAddress((void**)&p_woh, g_woh);
    cudaGetSymbolAddress((void**)&p_wol, g_wol);
    cudaGetSymbolAddress((void**)&p_ctx16, g_ctx16);

    cudaFuncSetAttribute(mma_gemm5<0>, cudaFuncAttributeMaxDynamicSharedMemorySize, GEMM_SMEM5);
    cudaFuncSetAttribute(mma_gemm5<1>, cudaFuncAttributeMaxDynamicSharedMemorySize, GEMM_SMEM5);
    cudaFuncSetAttribute(attn_mma5, cudaFuncAttributeMaxDynamicSharedMemorySize, ATTN_SMEM5);

    // 0) converts: query -> fp16; weights -> fp16 hi/lo
    cvt16_kernel<<<(TB * EE / 4 + 255) / 256, 256>>>(query, p_qry16, TB * EE / 4);
    split16_kernel<<<(FF * EE / 4 + 255) / 256, 256>>>(w_in, p_wih, p_wil, FF * EE / 4);
    split16_kernel<<<(EE * EE / 4 + 255) / 256, 256>>>(w_out, p_woh, p_wol, EE * EE / 4);

    // 1) QKV projection (fp16x2) -> q/k/v fp16 single (q pre-scaled)
    mma_gemm5<0><<<dim3(FF / 128, TB / 128), 256, GEMM_SMEM5>>>(p_qry16, p_wih, p_wil, b_in, nullptr);
    // 2) Flash attention (pure fp16 operands) -> ctx fp16
    attn_mma5<<<dim3(TQ / 128, BB * HH), 256, ATTN_SMEM5>>>();
    // 3) Output projection (fp16x2) -> fp32 out
    mma_gemm5<1><<<dim3(EE / 128, TB / 128), 256, GEMM_SMEM5>>>(p_ctx16, p_woh, p_wol, b_out, out);
}

// round 14
// speedup vs baseline: 7.6919x; 1.3099x over previous
#include <cuda_runtime.h>
#include <cuda_fp16.h>
#include <math.h>
#include <cstdint>

// Problem constants
#define TQ 2048
#define BB 2
#define EE 1024
#define HH 16
#define DD 64
#define TB 4096          // TQ*BB
#define FF 3072          // 3*EE

#define QSCALE (0.125f * 1.44269504088896f)   // d^-0.5 * log2(e)  (softmax uses ex2)

// Scratch (allocation-free rule: __device__ globals) — all single fp16
__device__ __half g_qry16[(size_t)TB * EE];          // A for gemm0
__device__ __half g_wi16[(size_t)FF * EE];           // W_in
__device__ __half g_wo16[(size_t)EE * EE];           // W_out
__device__ __half g_q16[(size_t)BB * HH * TQ * DD];  // Q (pre-scaled)
__device__ __half g_k16[(size_t)BB * HH * TQ * DD];  // K
__device__ __half g_v16[(size_t)BB * HH * TQ * DD];  // V
__device__ __half g_ctx16[(size_t)TB * EE];          // A for gemm1

// ============================================================================
// helpers
// ============================================================================
__device__ __forceinline__ uint32_t smem_u32(const void* p) {
    uint32_t a;
    asm("{ .reg .u64 t; cvta.to.shared.u64 t, %1; cvt.u32.u64 %0, t; }" : "=r"(a) : "l"(p));
    return a;
}
__device__ __forceinline__ uint32_t cvt2h(float x, float y) {
    __half2 h = __floats2half2_rn(x, y);
    return *(uint32_t*)&h;
}
__device__ __forceinline__ float ex2f(float x) {
    float y;
    asm("ex2.approx.f32 %0, %1;" : "=f"(y) : "f"(x));
    return y;
}
__device__ __forceinline__ void mma_f16(float* d, const uint32_t* a, const uint32_t* b) {
    asm volatile(
        "mma.sync.aligned.m16n8k16.row.col.f32.f16.f16.f32 "
        "{%0,%1,%2,%3}, {%4,%5,%6,%7}, {%8,%9}, {%0,%1,%2,%3};"
        : "+f"(d[0]), "+f"(d[1]), "+f"(d[2]), "+f"(d[3])
        : "r"(a[0]), "r"(a[1]), "r"(a[2]), "r"(a[3]), "r"(b[0]), "r"(b[1]));
}
#define LDSM_X4(R0,R1,R2,R3,ADDR) \
    asm volatile("ldmatrix.sync.aligned.m8n8.x4.shared.b16 {%0,%1,%2,%3}, [%4];" \
        : "=r"(R0), "=r"(R1), "=r"(R2), "=r"(R3) : "r"(ADDR))
#define LDSM_X4_T(R0,R1,R2,R3,ADDR) \
    asm volatile("ldmatrix.sync.aligned.m8n8.x4.trans.shared.b16 {%0,%1,%2,%3}, [%4];" \
        : "=r"(R0), "=r"(R1), "=r"(R2), "=r"(R3) : "r"(ADDR))
#define CP16(SM, GP) \
    asm volatile("cp.async.cg.shared.global [%0], [%1], 16;" :: "r"(SM), "l"(GP) : "memory")
#define CP_COMMIT() asm volatile("cp.async.commit_group;" ::: "memory")
#define CP_WAIT(N)  asm volatile("cp.async.wait_group %0;" :: "n"(N) : "memory")

// ============================================================================
// fp32 -> fp16 convert (elementwise, HBM-bound, one-time)
// ============================================================================
__global__ void cvt16_kernel(const float* __restrict__ src, __half* __restrict__ dst, int n4)
{
    int i = blockIdx.x * blockDim.x + threadIdx.x;
    if (i < n4) {
        float4 v = ((const float4*)src)[i];
        ((uint2*)dst)[i] = make_uint2(cvt2h(v.x, v.y), cvt2h(v.z, v.w));
    }
}

// ============================================================================
// GEMM v6 (pure fp16, single pass): 256 threads, 128x128 CTA tile,
// warp tile 64x32, 4-stage cp.async, pair-commit loop, 2 CTAs/SM.
// MODE 0: scatter q/k/v (fp16, q scaled). MODE 1: fp32 + bias.
// ============================================================================
#define GBK 32
#define GNC (EE / GBK)          // 32 chunks -> 16 pairs
#define GS_A  0
#define GS_B  8192
#define G_STAGE 16384
#define GEMM_SMEM6 (4 * G_STAGE)   // 65536

template <int MODE>
__global__ __launch_bounds__(256, 2)
void mma_gemm6(const __half* __restrict__ Ag, const __half* __restrict__ Bg,
               const float* __restrict__ bias, float* __restrict__ Cout)
{
    extern __shared__ char smem[];
    const uint32_t sb = smem_u32(smem);

    const int tid  = threadIdx.x;
    const int wid  = tid >> 5;
    const int lane = tid & 31;
    const int g    = lane >> 2;
    const int t    = lane & 3;
    const int wm   = (wid >> 2) << 6;   // 0 or 64
    const int wn   = (wid & 3) << 5;    // 0..96
    const int row0 = blockIdx.y * 128;
    const int col0 = blockIdx.x * 128;
    const int rK   = (lane & 7) + ((lane >> 4) & 1) * 8;
    const int cKb  = (lane >> 3) & 1;

    float acc[4][4][4];
#pragma unroll
    for (int i = 0; i < 4; i++)
#pragma unroll
        for (int j = 0; j < 4; j++)
#pragma unroll
            for (int k = 0; k < 4; k++) acc[i][j][k] = 0.0f;

    // copies of one chunk (no commit)
    auto issue_nc = [&](int c) {
        uint32_t st = sb + (uint32_t)(c & 3) * G_STAGE;
#pragma unroll
        for (int p = 0; p < 2; p++) {
            int id = tid + p * 256;
            int r  = id >> 2;
            int cg = id & 3;
            uint32_t so = (uint32_t)r * 64 + (uint32_t)((cg ^ ((r >> 1) & 3)) << 4);
            size_t ka = (size_t)(row0 + r) * EE + cg * 8 + (size_t)c * GBK;
            size_t kb = (size_t)(col0 + r) * EE + cg * 8 + (size_t)c * GBK;
            CP16(st + GS_A + so, Ag + ka);
            CP16(st + GS_B + so, Bg + kb);
        }
    };
    auto issue_pair = [&](int p) {
        issue_nc(2 * p);
        issue_nc(2 * p + 1);
        CP_COMMIT();
    };

    auto compute = [&](int c) {
        uint32_t base = sb + (uint32_t)(c & 3) * G_STAGE;
#pragma unroll
        for (int ks = 0; ks < 2; ks++) {
            uint32_t ah[4][4];
#pragma unroll
            for (int ma = 0; ma < 4; ma++) {
                int row  = wm + 16 * ma + (lane & 15);
                int cgrp = ks * 2 + (lane >> 4);
                uint32_t ad = base + GS_A + row * 64 + ((cgrp ^ ((row >> 1) & 3)) << 4);
                LDSM_X4(ah[ma][0], ah[ma][1], ah[ma][2], ah[ma][3], ad);
            }
            uint32_t bh2[4][2];
#pragma unroll
            for (int jj = 0; jj < 2; jj++) {
                int row  = wn + 16 * jj + rK;
                int cgrp = ks * 2 + cKb;
                uint32_t ad = base + GS_B + row * 64 + ((cgrp ^ ((row >> 1) & 3)) << 4);
                LDSM_X4(bh2[2 * jj][0], bh2[2 * jj][1], bh2[2 * jj + 1][0], bh2[2 * jj + 1][1], ad);
            }
#pragma unroll
            for (int ma = 0; ma < 4; ma++)
#pragma unroll
                for (int na = 0; na < 4; na++) mma_f16(acc[ma][na], ah[ma], bh2[na]);
        }
    };

    // ---- pair-commit main loop: one barrier per 2 chunks ----
    issue_pair(0);
    for (int p = 0; p < GNC / 2; p++) {
        CP_WAIT(0);            // pair p landed (this thread's copies)
        __syncthreads();       // visibility of all threads' copies + stage reuse guard
        if (p + 1 < GNC / 2) issue_pair(p + 1);   // overlaps compute of pair p
        compute(2 * p);
        compute(2 * p + 1);
    }

    // ---- epilogue ----
#pragma unroll
    for (int na = 0; na < 4; na++) {
        const int f0 = col0 + wn + 8 * na + 2 * t;
        const float b0 = bias[f0];
        const float b1 = bias[f0 + 1];
        if (MODE == 0) {
            int h     = f0 / 192;
            int rem   = f0 - 192 * h;
            int which = rem >> 6;
            int dd    = rem & 63;
            __half* dst = (which == 0) ? g_q16 : ((which == 1) ? g_k16 : g_v16);
            float mul = (which == 0) ? QSCALE : 1.0f;
#pragma unroll
            for (int ma = 0; ma < 4; ma++) {
                const float* d4 = acc[ma][na];
                int tb = row0 + wm + 16 * ma + g;
#pragma unroll
                for (int hh = 0; hh < 2; hh++) {
                    int tbx = tb + 8 * hh;
                    int tt = tbx >> 1, bb = tbx & 1;
                    size_t off = ((size_t)(bb * HH + h) * TQ + tt) * DD + dd;
                    *(uint32_t*)(dst + off) =
                        cvt2h((d4[2 * hh] + b0) * mul, (d4[2 * hh + 1] + b1) * mul);
                }
            }
        } else {
#pragma unroll
            for (int ma = 0; ma < 4; ma++) {
                const float* d4 = acc[ma][na];
                int r = row0 + wm + 16 * ma + g;
                *(float2*)(Cout + (size_t)r * EE + f0) = make_float2(d4[0] + b0, d4[1] + b1);
                *(float2*)(Cout + (size_t)(r + 8) * EE + f0) = make_float2(d4[2] + b0, d4[3] + b1);
            }
        }
    }
}

// ============================================================================
// Flash attention v5 (pure fp16 operands) — unchanged from round 13
// 3-stage KV ring (16KB/stage: K at +0, V at +8192), Q overlays stage 0.
// CTA: 128 q-rows of one (b,h), 8 warps x 16 rows, KV tiles of 64. 2 CTAs/SM.
// ============================================================================
#define AKV_ST5 16384              // per stage: K 0..8K, V 8K..16K
#define ATTN_SMEM5 (3 * AKV_ST5)   // 49152 ; Q (16KB) overlays stage 0 exactly
#define NTILES (TQ / 64)           // 32

__global__ __launch_bounds__(256, 2)
void attn_mma5()
{
    extern __shared__ char sm[];
    const uint32_t sb = smem_u32(sm);

    const int tid  = threadIdx.x;
    const int wid  = tid >> 5;
    const int lane = tid & 31;
    const int g    = lane >> 2;
    const int t    = lane & 3;

    const int bh = blockIdx.y;
    const int b  = bh >> 4;
    const int h  = bh & 15;
    const size_t base = (size_t)bh * TQ * DD;
    const int t0 = blockIdx.x * 128;
    const int m0 = wid * 16;

    const int rK  = (lane & 7) + ((lane >> 4) & 1) * 8;
    const int cKb = (lane >> 3) & 1;
    const int rV  = (lane & 7) + ((lane >> 3) & 1) * 8;
    const int cVb = (lane >> 4) & 1;

    // stage(tile j) = (j+1) % 3
    auto issueQ = [&]() {   // into [0, 16K) = stage 0
#pragma unroll
        for (int p = 0; p < 4; p++) {
            int id = tid + p * 256;
            int r = id >> 3, cgp = id & 7;
            uint32_t so = (uint32_t)r * 128 + ((cgp ^ (r & 7)) << 4);
            CP16(sb + so, g_q16 + base + (size_t)(t0 + r) * DD + cgp * 8);
        }
        CP_COMMIT();
    };
    auto issueKV = [&](int st, int stage) {
        uint32_t kvb = sb + (uint32_t)stage * AKV_ST5;
#pragma unroll
        for (int p = 0; p < 2; p++) {
            int id = tid + p * 256;
            int r = id >> 3, cgp = id & 7;
            uint32_t so = (uint32_t)r * 128 + ((cgp ^ (r & 7)) << 4);
            size_t go = base + (size_t)(st + r) * DD + cgp * 8;
            CP16(kvb + so,        g_k16 + go);
            CP16(kvb + 8192 + so, g_v16 + go);
        }
        CP_COMMIT();
    };

    issueQ();
    issueKV(0, 1);
    issueKV(64, 2);
    CP_WAIT(2);           // this thread's Q copies landed
    __syncthreads();      // make ALL threads' Q copies visible before ldmatrix

    // ---- Q fragments (persistent, fp16 single) ----
    uint32_t qh[4][4];
    {
        int row = m0 + (lane & 15);
#pragma unroll
        for (int ks = 0; ks < 4; ks++) {
            int cgrp = ks * 2 + (lane >> 4);
            uint32_t a = sb + row * 128 + ((cgrp ^ (row & 7)) << 4);
            LDSM_X4(qh[ks][0], qh[ks][1], qh[ks][2], qh[ks][3], a);
        }
    }
    __syncthreads();      // all warps done reading Q; stage 0 reusable

    float O[8][4];
#pragma unroll
    for (int j = 0; j < 8; j++)
#pragma unroll
        for (int k = 0; k < 4; k++) O[j][k] = 0.0f;
    float mrow0 = -1e30f, mrow1 = -1e30f, lrow0 = 0.0f, lrow1 = 0.0f;

    for (int i = 0; i < NTILES; i++) {
        if (i + 1 < NTILES) { CP_WAIT(1); } else { CP_WAIT(0); }  // tile i landed
        __syncthreads();                      // visibility + stage-reuse guard
        if (i + 2 < NTILES) issueKV((i + 2) * 64, (i + 3) % 3);

        uint32_t kvb = sb + (uint32_t)((i + 1) % 3) * AKV_ST5;

        // ---- S = Q K^T (single pass) ----
        float S[8][4];
#pragma unroll
        for (int j = 0; j < 8; j++)
#pragma unroll
            for (int k = 0; k < 4; k++) S[j][k] = 0.0f;

#pragma unroll
        for (int ks = 0; ks < 4; ks++) {
            uint32_t bh_[8][2];
#pragma unroll
            for (int jj = 0; jj < 4; jj++) {
                int row  = 16 * jj + rK;
                int cgrp = ks * 2 + cKb;
                uint32_t a = kvb + row * 128 + ((cgrp ^ (row & 7)) << 4);
                LDSM_X4(bh_[2 * jj][0], bh_[2 * jj][1], bh_[2 * jj + 1][0], bh_[2 * jj + 1][1], a);
            }
#pragma unroll
            for (int j = 0; j < 8; j++) mma_f16(S[j], qh[ks], bh_[j]);
        }

        // ---- online softmax (base-2) ----
        float mx0 = -1e30f, mx1 = -1e30f;
#pragma unroll
        for (int j = 0; j < 8; j++) {
            mx0 = fmaxf(mx0, fmaxf(S[j][0], S[j][1]));
            mx1 = fmaxf(mx1, fmaxf(S[j][2], S[j][3]));
        }
        mx0 = fmaxf(mx0, __shfl_xor_sync(0xffffffffu, mx0, 1));
        mx0 = fmaxf(mx0, __shfl_xor_sync(0xffffffffu, mx0, 2));
        mx1 = fmaxf(mx1, __shfl_xor_sync(0xffffffffu, mx1, 1));
        mx1 = fmaxf(mx1, __shfl_xor_sync(0xffffffffu, mx1, 2));
        float mn0 = fmaxf(mrow0, mx0), mn1 = fmaxf(mrow1, mx1);
        float sc0 = ex2f(mrow0 - mn0), sc1 = ex2f(mrow1 - mn1);
        float s0 = 0.0f, s1 = 0.0f;
#pragma unroll
        for (int j = 0; j < 8; j++) {
            S[j][0] = ex2f(S[j][0] - mn0);
            S[j][1] = ex2f(S[j][1] - mn0);
            S[j][2] = ex2f(S[j][2] - mn1);
            S[j][3] = ex2f(S[j][3] - mn1);
            s0 += S[j][0] + S[j][1];
            s1 += S[j][2] + S[j][3];
        }
        s0 += __shfl_xor_sync(0xffffffffu, s0, 1);
        s0 += __shfl_xor_sync(0xffffffffu, s0, 2);
        s1 += __shfl_xor_sync(0xffffffffu, s1, 1);
        s1 += __shfl_xor_sync(0xffffffffu, s1, 2);
        lrow0 = lrow0 * sc0 + s0;
        lrow1 = lrow1 * sc1 + s1;
        mrow0 = mn0;
        mrow1 = mn1;
#pragma unroll
        for (int j = 0; j < 8; j++) {
            O[j][0] *= sc0; O[j][1] *= sc0;
            O[j][2] *= sc1; O[j][3] *= sc1;
        }

        // ---- P fragments (fp16 single, straight from S accumulators) ----
        uint32_t ph[4][4];
#pragma unroll
        for (int kk = 0; kk < 4; kk++) {
            ph[kk][0] = cvt2h(S[2 * kk][0],     S[2 * kk][1]);
            ph[kk][1] = cvt2h(S[2 * kk][2],     S[2 * kk][3]);
            ph[kk][2] = cvt2h(S[2 * kk + 1][0], S[2 * kk + 1][1]);
            ph[kk][3] = cvt2h(S[2 * kk + 1][2], S[2 * kk + 1][3]);
        }

        // ---- O += P V (single pass) ----
#pragma unroll
        for (int kk = 0; kk < 4; kk++) {
            uint32_t vh_[8][2];
#pragma unroll
            for (int jj = 0; jj < 4; jj++) {
                int row  = kk * 16 + rV;
                int cgrp = jj * 2 + cVb;
                uint32_t a = kvb + 8192 + row * 128 + ((cgrp ^ (row & 7)) << 4);
                LDSM_X4_T(vh_[2 * jj][0], vh_[2 * jj][1], vh_[2 * jj + 1][0], vh_[2 * jj + 1][1], a);
            }
#pragma unroll
            for (int j = 0; j < 8; j++) mma_f16(O[j], ph[kk], vh_[j]);
        }
    }

    // ---- epilogue: ctx fp16 single, layout [TB, EE] ----
    float inv0 = 1.0f / lrow0, inv1 = 1.0f / lrow1;
    int qr0 = t0 + m0 + g;
    int qr1 = qr0 + 8;
#pragma unroll
    for (int j = 0; j < 8; j++) {
        int col = h * 64 + 8 * j + 2 * t;
        *(uint32_t*)(g_ctx16 + (size_t)(qr0 * BB + b) * EE + col) =
            cvt2h(O[j][0] * inv0, O[j][1] * inv0);
        *(uint32_t*)(g_ctx16 + (size_t)(qr1 * BB + b) * EE + col) =
            cvt2h(O[j][2] * inv1, O[j][3] * inv1);
    }
}

// ============================================================================
// Launch
// ============================================================================
extern "C" void kernel_launch(void* const* d_in, const int* in_sizes, int n_in,
                              void* d_out, int out_size)
{
    const float* query = (const float*)d_in[0];
    const float* w_in  = (const float*)d_in[1];
    const float* b_in  = (const float*)d_in[2];
    const float* w_out = (const float*)d_in[3];
    const float* b_out = (const float*)d_in[4];
    float* out = (float*)d_out;

    __half *p_qry16, *p_wi16, *p_wo16, *p_ctx16;
    cudaGetSymbolAddress((void**)&p_qry16, g_qry16);
    cudaGetSymbolAddress((void**)&p_wi16, g_wi16);
    cudaGetSymbolAddress((void**)&p_wo16, g_wo16);
    cudaGetSymbolAddress((void**)&p_ctx16, g_ctx16);

    cudaFuncSetAttribute(mma_gemm6<0>, cudaFuncAttributeMaxDynamicSharedMemorySize, GEMM_SMEM6);
    cudaFuncSetAttribute(mma_gemm6<1>, cudaFuncAttributeMaxDynamicSharedMemorySize, GEMM_SMEM6);
    cudaFuncSetAttribute(attn_mma5, cudaFuncAttributeMaxDynamicSharedMemorySize, ATTN_SMEM5);

    // 0) converts: everything -> fp16 single
    cvt16_kernel<<<(TB * EE / 4 + 255) / 256, 256>>>(query, p_qry16, TB * EE / 4);
    cvt16_kernel<<<(FF * EE / 4 + 255) / 256, 256>>>(w_in, p_wi16, FF * EE / 4);
    cvt16_kernel<<<(EE * EE / 4 + 255) / 256, 256>>>(w_out, p_wo16, EE * EE / 4);

    // 1) QKV projection (fp16) -> q/k/v fp16 (q pre-scaled)
    mma_gemm6<0><<<dim3(FF / 128, TB / 128), 256, GEMM_SMEM6>>>(p_qry16, p_wi16, b_in, nullptr);
    // 2) Flash attention (pure fp16 operands) -> ctx fp16
    attn_mma5<<<dim3(TQ / 128, BB * HH), 256, ATTN_SMEM5>>>();
    // 3) Output projection (fp16) -> fp32 out
    mma_gemm6<1><<<dim3(EE / 128, TB / 128), 256, GEMM_SMEM6>>>(p_ctx16, p_wo16, b_out, out);
}